// round 6
// baseline (speedup 1.0000x reference)
#include <cuda_runtime.h>
#include <cuda_bf16.h>
#include <cstdint>

// Problem constants
constexpr int B   = 4;
constexpr int S   = 2048;
constexpr int HID = 512;
constexpr int NH  = 8;
constexpr int DH  = 64;
constexpr int M   = B * S;       // 8192

// Scratch (device globals — no runtime allocation allowed)
__device__ __nv_bfloat16 g_wsplit[2][4][HID * HID];   // [hi/lo][Wq,Wk,Wv,Wo]
__device__ __nv_bfloat16 g_xh[3][M * HID], g_xl[3][M * HID];  // q,k,v inputs
__device__ __nv_bfloat16 g_qh[M * HID], g_ql[M * HID];
__device__ __nv_bfloat16 g_kh[M * HID], g_kl[M * HID];
__device__ __nv_bfloat16 g_vh[M * HID], g_vl[M * HID];
__device__ __nv_bfloat16 g_oh[M * HID], g_ol[M * HID];

// ---------------------------------------------------------------------------
// mma.sync / ldmatrix / cp.async helpers (plain sm_80+ PTX)
// ---------------------------------------------------------------------------
__device__ __forceinline__ uint32_t smem_u32(const void* p) {
  uint32_t a;
  asm("{ .reg .u64 t; cvta.to.shared.u64 t, %1; cvt.u32.u64 %0, t; }"
      : "=r"(a) : "l"(p));
  return a;
}

#define LDMX4(r0, r1, r2, r3, addr)                                       \
  asm volatile(                                                           \
      "ldmatrix.sync.aligned.m8n8.x4.shared.b16 {%0,%1,%2,%3}, [%4];"     \
      : "=r"(r0), "=r"(r1), "=r"(r2), "=r"(r3) : "r"(addr))

#define LDMX4T(r0, r1, r2, r3, addr)                                      \
  asm volatile(                                                           \
      "ldmatrix.sync.aligned.m8n8.x4.trans.shared.b16 {%0,%1,%2,%3}, [%4];" \
      : "=r"(r0), "=r"(r1), "=r"(r2), "=r"(r3) : "r"(addr))

#define CP_ASYNC16(dst, src)                                              \
  asm volatile("cp.async.cg.shared.global [%0], [%1], 16;" ::             \
                   "r"(dst), "l"(src))
#define CP_COMMIT() asm volatile("cp.async.commit_group;" ::: "memory")
#define CP_WAIT0() asm volatile("cp.async.wait_group 0;" ::: "memory")
#define CP_WAIT1() asm volatile("cp.async.wait_group 1;" ::: "memory")

__device__ __forceinline__ void mma_bf16(float& c0, float& c1, float& c2,
                                         float& c3, uint32_t a0, uint32_t a1,
                                         uint32_t a2, uint32_t a3,
                                         uint32_t b0, uint32_t b1) {
  asm volatile(
      "mma.sync.aligned.m16n8k16.row.col.f32.bf16.bf16.f32 "
      "{%0,%1,%2,%3}, {%4,%5,%6,%7}, {%8,%9}, {%0,%1,%2,%3};"
      : "+f"(c0), "+f"(c1), "+f"(c2), "+f"(c3)
      : "r"(a0), "r"(a1), "r"(a2), "r"(a3), "r"(b0), "r"(b1));
}

__device__ __forceinline__ uint32_t pack_bf16(float a, float b) {
  __nv_bfloat162 t = __floats2bfloat162_rn(a, b);
  return *(uint32_t*)&t;
}

// ---------------------------------------------------------------------------
// fp32 -> (bf16 hi, bf16 lo) splits. Batched over blockIdx.y.
// ---------------------------------------------------------------------------
struct SplitBatch {
  const float* src[4];
  __nv_bfloat16* hi[4];
  __nv_bfloat16* lo[4];
};

__global__ __launch_bounds__(256) void split_batch_kernel(SplitBatch sb,
                                                          int n4) {
  int i = blockIdx.x * blockDim.x + threadIdx.x;
  if (i >= n4) return;
  int z = blockIdx.y;
  float4 v = ((const float4*)sb.src[z])[i];
  float hx = __bfloat162float(__float2bfloat16(v.x));
  float hy = __bfloat162float(__float2bfloat16(v.y));
  float hz = __bfloat162float(__float2bfloat16(v.z));
  float hw = __bfloat162float(__float2bfloat16(v.w));
  uint2 ho, lw;
  ho.x = pack_bf16(v.x, v.y);
  ho.y = pack_bf16(v.z, v.w);
  lw.x = pack_bf16(v.x - hx, v.y - hy);
  lw.y = pack_bf16(v.z - hz, v.w - hw);
  ((uint2*)sb.hi[z])[i] = ho;
  ((uint2*)sb.lo[z])[i] = lw;
}

// ---------------------------------------------------------------------------
// HMMA bf16x3 GEMM-NT: C = A @ W^T (fp32 accuracy via hi/lo splits).
// CTA 128x128, 8 warps, warp 64x32 (4x4 m16n8k16).
// 2-stage cp.async pipeline, k-chunk = 32 (16 chunks of 512).
// Row stride 80B: 16B-aligned, ldmatrix conflict-free. Stage 40KB, 2 stages.
// grid.z batches independent (A, W, C) triples.
// ---------------------------------------------------------------------------
constexpr int RB = 80;                    // smem row stride bytes
constexpr int G_TILE = 128 * RB;          // 10240
constexpr int T_AH = 0, T_AL = G_TILE, T_WH = 2 * G_TILE, T_WL = 3 * G_TILE;
constexpr int G_STG = 4 * G_TILE;         // 40960
constexpr int GEMM_SMEM = 2 * G_STG;      // 81920

struct GemmBatch {
  const __nv_bfloat16* ah[3];
  const __nv_bfloat16* al[3];
  const __nv_bfloat16* wh[3];
  const __nv_bfloat16* wl[3];
  __nv_bfloat16* ch[3];
  __nv_bfloat16* cl[3];
};

template <bool SPLIT>
__global__ __launch_bounds__(256) void gemm_tc_hmma(GemmBatch p,
                                                    float* __restrict__ C) {
  extern __shared__ __align__(128) char smem[];
  const uint32_t sb = smem_u32(smem);
  const int t = threadIdx.x;
  const int wid = t >> 5, l = t & 31;
  const int wm = wid >> 2;
  const int wn = wid & 3;
  const int m0 = blockIdx.y * 128;
  const int n0 = blockIdx.x * 128;
  const int z = blockIdx.z;

  const __nv_bfloat16* srcs[4] = {p.ah[z], p.al[z], p.wh[z], p.wl[z]};
  const int brow[4] = {m0, m0, n0, n0};

  auto issue = [&](int stage, int kc) {
    const int koff = kc * 32;
#pragma unroll
    for (int i = 0; i < 8; i++) {
      int idx = t + i * 256;
      int comp = idx >> 9;               // 0..3
      int r = (idx >> 2) & 127;          // row
      int c = idx & 3;                   // 16B group (0..3)
      const __nv_bfloat16* src =
          srcs[comp] + (size_t)(brow[comp] + r) * HID + koff + c * 8;
      uint32_t dst = sb + stage * G_STG + comp * G_TILE + r * RB + c * 16;
      CP_ASYNC16(dst, src);
    }
  };

  issue(0, 0);
  CP_COMMIT();

  float acc[4][4][4] = {};

  const int a_row = (l & 15);
  const int a_koff = ((l >> 4) & 1) * 16;
  const int b_row = (l & 7) + ((l >> 4) & 1) * 8;
  const int b_koff = ((l >> 3) & 1) * 16;

  for (int kc = 0; kc < 16; kc++) {
    if (kc + 1 < 16) {
      issue((kc + 1) & 1, kc + 1);
      CP_COMMIT();
      CP_WAIT1();
    } else {
      CP_WAIT0();
    }
    __syncthreads();
    const uint32_t st = sb + (kc & 1) * G_STG;

#pragma unroll
    for (int ks = 0; ks < 2; ks++) {
      const int kb = ks * 32;
      uint32_t ah[4][4], al[4][4], bh[8], bl[8];
#pragma unroll
      for (int mt = 0; mt < 4; mt++) {
        uint32_t ra = (wm * 64 + mt * 16 + a_row) * RB + kb + a_koff;
        LDMX4(ah[mt][0], ah[mt][1], ah[mt][2], ah[mt][3], st + T_AH + ra);
        LDMX4(al[mt][0], al[mt][1], al[mt][2], al[mt][3], st + T_AL + ra);
      }
#pragma unroll
      for (int np = 0; np < 2; np++) {
        uint32_t rb = (wn * 32 + np * 16 + b_row) * RB + kb + b_koff;
        LDMX4(bh[np * 4 + 0], bh[np * 4 + 1], bh[np * 4 + 2], bh[np * 4 + 3],
              st + T_WH + rb);
        LDMX4(bl[np * 4 + 0], bl[np * 4 + 1], bl[np * 4 + 2], bl[np * 4 + 3],
              st + T_WL + rb);
      }
#pragma unroll
      for (int mt = 0; mt < 4; mt++)
#pragma unroll
        for (int nt = 0; nt < 4; nt++) {
          float* c = acc[mt][nt];
          mma_bf16(c[0], c[1], c[2], c[3], ah[mt][0], ah[mt][1], ah[mt][2],
                   ah[mt][3], bh[nt * 2], bh[nt * 2 + 1]);
          mma_bf16(c[0], c[1], c[2], c[3], ah[mt][0], ah[mt][1], ah[mt][2],
                   ah[mt][3], bl[nt * 2], bl[nt * 2 + 1]);
          mma_bf16(c[0], c[1], c[2], c[3], al[mt][0], al[mt][1], al[mt][2],
                   al[mt][3], bh[nt * 2], bh[nt * 2 + 1]);
        }
    }
    __syncthreads();
  }

  const int er = l >> 2, ec = (l & 3) * 2;
#pragma unroll
  for (int mt = 0; mt < 4; mt++) {
    int row = m0 + wm * 64 + mt * 16 + er;
#pragma unroll
    for (int nt = 0; nt < 4; nt++) {
      int col = n0 + wn * 32 + nt * 8 + ec;
      float* a = acc[mt][nt];
      if constexpr (SPLIT) {
        float h0 = __bfloat162float(__float2bfloat16(a[0]));
        float h1 = __bfloat162float(__float2bfloat16(a[1]));
        float h2 = __bfloat162float(__float2bfloat16(a[2]));
        float h3 = __bfloat162float(__float2bfloat16(a[3]));
        size_t i0 = (size_t)row * HID + col;
        size_t i1 = (size_t)(row + 8) * HID + col;
        *(uint32_t*)&p.ch[z][i0] = pack_bf16(a[0], a[1]);
        *(uint32_t*)&p.cl[z][i0] = pack_bf16(a[0] - h0, a[1] - h1);
        *(uint32_t*)&p.ch[z][i1] = pack_bf16(a[2], a[3]);
        *(uint32_t*)&p.cl[z][i1] = pack_bf16(a[2] - h2, a[3] - h3);
      } else {
        *(float2*)&C[(size_t)row * HID + col] = make_float2(a[0], a[1]);
        *(float2*)&C[(size_t)(row + 8) * HID + col] = make_float2(a[2], a[3]);
      }
    }
  }
}

// ---------------------------------------------------------------------------
// HMMA flash attention (bf16x3, fp32 softmax) — unchanged from round 5.
// ---------------------------------------------------------------------------
constexpr int RS = 72;                         // Q smem row stride (bf16)
constexpr int AQ_H = 0;
constexpr int AQ_L = 128 * RS * 2;
constexpr int STG0 = 2 * 128 * RS * 2;         // 36864
constexpr int KV_COMP = 64 * RS * 2;           // 9216 per component
constexpr int STG_SZ = 4 * KV_COMP;            // 36864
constexpr int ATTN_SMEM = STG0 + 2 * STG_SZ;   // 110592

__global__ __launch_bounds__(256) void attn_hmma(
    const __nv_bfloat16* __restrict__ Qh, const __nv_bfloat16* __restrict__ Ql,
    const __nv_bfloat16* __restrict__ Kh, const __nv_bfloat16* __restrict__ Kl,
    const __nv_bfloat16* __restrict__ Vh, const __nv_bfloat16* __restrict__ Vl,
    const int* __restrict__ valid_lens, __nv_bfloat16* __restrict__ Oh,
    __nv_bfloat16* __restrict__ Ol) {
  extern __shared__ __align__(128) char smem[];
  const uint32_t sb = smem_u32(smem);
  const int qt = blockIdx.x, h = blockIdx.y, b = blockIdx.z;
  const int t = threadIdx.x;
  const int wid = t >> 5, l = t & 31;
  const int q0 = qt * 128;
  const int vlen = valid_lens[b];
  const int ntiles = (vlen + 63) >> 6;

  const __nv_bfloat16* kv_src[4] = {Kh, Kl, Vh, Vl};

  auto issue_tile = [&](int stage, int kbase) {
#pragma unroll
    for (int i = 0; i < 8; i++) {
      int idx = t + i * 256;
      int comp = idx >> 9;
      int r = (idx >> 3) & 63;
      int c = idx & 7;
      const __nv_bfloat16* src =
          kv_src[comp] + (size_t)(b * S + kbase + r) * HID + h * DH + c * 8;
      uint32_t dst =
          sb + STG0 + stage * STG_SZ + comp * KV_COMP + r * (RS * 2) + c * 16;
      CP_ASYNC16(dst, src);
    }
  };

  issue_tile(0, 0);
  CP_COMMIT();
#pragma unroll
  for (int i = 0; i < 4; i++) {
    int v = t + i * 256;
    int row = v >> 3, c = v & 7;
    size_t g = (size_t)(b * S + q0 + row) * HID + h * DH + c * 8;
    uint32_t so = row * (RS * 2) + c * 16;
    *(uint4*)(smem + AQ_H + so) = *(const uint4*)(Qh + g);
    *(uint4*)(smem + AQ_L + so) = *(const uint4*)(Ql + g);
  }
  __syncthreads();

  const int a_row = (l & 15);
  const int a_koff = ((l >> 4) & 1) * 16;
  const int b_row = (l & 7) + ((l >> 4) & 1) * 8;
  const int b_koff = ((l >> 3) & 1) * 16;
  const int v_row = (l & 7) + ((l >> 3) & 1) * 8;
  const int v_col = ((l >> 4) & 1) * 16;
  const int cb = (l & 3) * 2;

  uint32_t qh[4][4], ql[4][4];
#pragma unroll
  for (int ks = 0; ks < 4; ks++) {
    uint32_t ra = (wid * 16 + a_row) * (RS * 2) + ks * 32 + a_koff;
    LDMX4(qh[ks][0], qh[ks][1], qh[ks][2], qh[ks][3], sb + AQ_H + ra);
    LDMX4(ql[ks][0], ql[ks][1], ql[ks][2], ql[ks][3], sb + AQ_L + ra);
  }

  float oacc[8][4] = {};
  float m0r = -1e30f, m1r = -1e30f, l0r = 0.f, l1r = 0.f;

  for (int kt = 0; kt < ntiles; kt++) {
    const int kbase = kt * 64;
    const uint32_t kb_h = sb + STG0 + (kt & 1) * STG_SZ;
    const uint32_t kb_l = kb_h + KV_COMP;
    const uint32_t vb_h = kb_h + 2 * KV_COMP;
    const uint32_t vb_l = kb_h + 3 * KV_COMP;

    CP_WAIT0();
    __syncthreads();
    if (kt + 1 < ntiles) {
      issue_tile((kt + 1) & 1, kbase + 64);
      CP_COMMIT();
    }

    float sc[8][4];
#pragma unroll
    for (int nt = 0; nt < 8; nt++)
#pragma unroll
      for (int c = 0; c < 4; c++) sc[nt][c] = 0.f;
#pragma unroll
    for (int ks = 0; ks < 4; ks++) {
      uint32_t khf[16], klf[16];
#pragma unroll
      for (int np = 0; np < 4; np++) {
        uint32_t rb = (np * 16 + b_row) * (RS * 2) + ks * 32 + b_koff;
        LDMX4(khf[np * 4 + 0], khf[np * 4 + 1], khf[np * 4 + 2],
              khf[np * 4 + 3], kb_h + rb);
        LDMX4(klf[np * 4 + 0], klf[np * 4 + 1], klf[np * 4 + 2],
              klf[np * 4 + 3], kb_l + rb);
      }
#pragma unroll
      for (int nt = 0; nt < 8; nt++) {
        float* c = sc[nt];
        mma_bf16(c[0], c[1], c[2], c[3], qh[ks][0], qh[ks][1], qh[ks][2],
                 qh[ks][3], khf[nt * 2], khf[nt * 2 + 1]);
        mma_bf16(c[0], c[1], c[2], c[3], qh[ks][0], qh[ks][1], qh[ks][2],
                 qh[ks][3], klf[nt * 2], klf[nt * 2 + 1]);
        mma_bf16(c[0], c[1], c[2], c[3], ql[ks][0], ql[ks][1], ql[ks][2],
                 ql[ks][3], khf[nt * 2], khf[nt * 2 + 1]);
      }
    }

#pragma unroll
    for (int nt = 0; nt < 8; nt++)
#pragma unroll
      for (int c = 0; c < 4; c++) sc[nt][c] *= 0.125f;
    if (kbase + 64 > vlen) {
#pragma unroll
      for (int nt = 0; nt < 8; nt++) {
        int k0 = kbase + nt * 8 + cb;
        if (k0 >= vlen) { sc[nt][0] = -1e30f; sc[nt][2] = -1e30f; }
        if (k0 + 1 >= vlen) { sc[nt][1] = -1e30f; sc[nt][3] = -1e30f; }
      }
    }

    float rm0 = -1e30f, rm1 = -1e30f;
#pragma unroll
    for (int nt = 0; nt < 8; nt++) {
      rm0 = fmaxf(rm0, fmaxf(sc[nt][0], sc[nt][1]));
      rm1 = fmaxf(rm1, fmaxf(sc[nt][2], sc[nt][3]));
    }
    rm0 = fmaxf(rm0, __shfl_xor_sync(0xffffffffu, rm0, 1));
    rm0 = fmaxf(rm0, __shfl_xor_sync(0xffffffffu, rm0, 2));
    rm1 = fmaxf(rm1, __shfl_xor_sync(0xffffffffu, rm1, 1));
    rm1 = fmaxf(rm1, __shfl_xor_sync(0xffffffffu, rm1, 2));
    float mn0 = fmaxf(m0r, rm0), mn1 = fmaxf(m1r, rm1);
    float corr0 = __expf(m0r - mn0), corr1 = __expf(m1r - mn1);

    uint32_t ph[8][2], pl[8][2];
    float rs0 = 0.f, rs1 = 0.f;
#pragma unroll
    for (int nt = 0; nt < 8; nt++) {
      float p0 = __expf(sc[nt][0] - mn0);
      float p1 = __expf(sc[nt][1] - mn0);
      float p2 = __expf(sc[nt][2] - mn1);
      float p3 = __expf(sc[nt][3] - mn1);
      rs0 += p0 + p1;
      rs1 += p2 + p3;
      float h0 = __bfloat162float(__float2bfloat16(p0));
      float h1 = __bfloat162float(__float2bfloat16(p1));
      float h2 = __bfloat162float(__float2bfloat16(p2));
      float h3 = __bfloat162float(__float2bfloat16(p3));
      ph[nt][0] = pack_bf16(p0, p1);
      ph[nt][1] = pack_bf16(p2, p3);
      pl[nt][0] = pack_bf16(p0 - h0, p1 - h1);
      pl[nt][1] = pack_bf16(p2 - h2, p3 - h3);
    }
    rs0 += __shfl_xor_sync(0xffffffffu, rs0, 1);
    rs0 += __shfl_xor_sync(0xffffffffu, rs0, 2);
    rs1 += __shfl_xor_sync(0xffffffffu, rs1, 1);
    rs1 += __shfl_xor_sync(0xffffffffu, rs1, 2);
    l0r = l0r * corr0 + rs0;
    l1r = l1r * corr1 + rs1;
    m0r = mn0;
    m1r = mn1;
#pragma unroll
    for (int nt = 0; nt < 8; nt++) {
      oacc[nt][0] *= corr0;
      oacc[nt][1] *= corr0;
      oacc[nt][2] *= corr1;
      oacc[nt][3] *= corr1;
    }

#pragma unroll
    for (int ks = 0; ks < 4; ks++) {
      uint32_t vhf[16], vlf[16];
#pragma unroll
      for (int np = 0; np < 4; np++) {
        uint32_t rv = (ks * 16 + v_row) * (RS * 2) + np * 32 + v_col;
        LDMX4T(vhf[np * 4 + 0], vhf[np * 4 + 1], vhf[np * 4 + 2],
               vhf[np * 4 + 3], vb_h + rv);
        LDMX4T(vlf[np * 4 + 0], vlf[np * 4 + 1], vlf[np * 4 + 2],
               vlf[np * 4 + 3], vb_l + rv);
      }
      uint32_t a0 = ph[2 * ks][0], a1 = ph[2 * ks][1];
      uint32_t a2 = ph[2 * ks + 1][0], a3 = ph[2 * ks + 1][1];
      uint32_t e0 = pl[2 * ks][0], e1 = pl[2 * ks][1];
      uint32_t e2 = pl[2 * ks + 1][0], e3 = pl[2 * ks + 1][1];
#pragma unroll
      for (int nt = 0; nt < 8; nt++) {
        float* c = oacc[nt];
        mma_bf16(c[0], c[1], c[2], c[3], a0, a1, a2, a3, vhf[nt * 2],
                 vhf[nt * 2 + 1]);
        mma_bf16(c[0], c[1], c[2], c[3], a0, a1, a2, a3, vlf[nt * 2],
                 vlf[nt * 2 + 1]);
        mma_bf16(c[0], c[1], c[2], c[3], e0, e1, e2, e3, vhf[nt * 2],
                 vhf[nt * 2 + 1]);
      }
    }
  }

  float inv0 = 1.f / l0r, inv1 = 1.f / l1r;
  int r0 = q0 + wid * 16 + (l >> 2);
#pragma unroll
  for (int nt = 0; nt < 8; nt++) {
    int col = h * DH + nt * 8 + cb;
    float o0 = oacc[nt][0] * inv0, o1 = oacc[nt][1] * inv0;
    float o2 = oacc[nt][2] * inv1, o3 = oacc[nt][3] * inv1;
    float h0 = __bfloat162float(__float2bfloat16(o0));
    float h1 = __bfloat162float(__float2bfloat16(o1));
    float h2 = __bfloat162float(__float2bfloat16(o2));
    float h3 = __bfloat162float(__float2bfloat16(o3));
    size_t i0 = (size_t)(b * S + r0) * HID + col;
    size_t i1 = (size_t)(b * S + r0 + 8) * HID + col;
    *(uint32_t*)&Oh[i0] = pack_bf16(o0, o1);
    *(uint32_t*)&Ol[i0] = pack_bf16(o0 - h0, o1 - h1);
    *(uint32_t*)&Oh[i1] = pack_bf16(o2, o3);
    *(uint32_t*)&Ol[i1] = pack_bf16(o2 - h2, o3 - h3);
  }
}

// ---------------------------------------------------------------------------
extern "C" void kernel_launch(void* const* d_in, const int* in_sizes, int n_in,
                              void* d_out, int out_size) {
  const float* queries = (const float*)d_in[0];
  const float* keys    = (const float*)d_in[1];
  const float* values  = (const float*)d_in[2];
  const int*   vlens   = (const int*)d_in[3];
  const float* W[4]    = {(const float*)d_in[4], (const float*)d_in[5],
                          (const float*)d_in[6], (const float*)d_in[7]};
  float* out = (float*)d_out;

  __nv_bfloat16 *wsp, *xh, *xl, *qh, *ql, *kh, *kl, *vh, *vl, *oh, *ol;
  cudaGetSymbolAddress((void**)&wsp, g_wsplit);
  cudaGetSymbolAddress((void**)&xh, g_xh);
  cudaGetSymbolAddress((void**)&xl, g_xl);
  cudaGetSymbolAddress((void**)&qh, g_qh);
  cudaGetSymbolAddress((void**)&ql, g_ql);
  cudaGetSymbolAddress((void**)&kh, g_kh);
  cudaGetSymbolAddress((void**)&kl, g_kl);
  cudaGetSymbolAddress((void**)&vh, g_vh);
  cudaGetSymbolAddress((void**)&vl, g_vl);
  cudaGetSymbolAddress((void**)&oh, g_oh);
  cudaGetSymbolAddress((void**)&ol, g_ol);
  const int WSZ = HID * HID;
  const int XSZ = M * HID;
  __nv_bfloat16* wh[4];
  __nv_bfloat16* wl4[4];
  for (int i = 0; i < 4; i++) {
    wh[i] = wsp + i * WSZ;            // g_wsplit[0][i]
    wl4[i] = wsp + (4 + i) * WSZ;     // g_wsplit[1][i]
  }

  cudaFuncSetAttribute(gemm_tc_hmma<true>,
                       cudaFuncAttributeMaxDynamicSharedMemorySize, GEMM_SMEM);
  cudaFuncSetAttribute(gemm_tc_hmma<false>,
                       cudaFuncAttributeMaxDynamicSharedMemorySize, GEMM_SMEM);
  cudaFuncSetAttribute(attn_hmma,
                       cudaFuncAttributeMaxDynamicSharedMemorySize, ATTN_SMEM);

  // --- splits: 4 weights in one launch, 3 activations in one launch ---
  SplitBatch wsb = {};
  for (int i = 0; i < 4; i++) {
    wsb.src[i] = W[i];
    wsb.hi[i] = wh[i];
    wsb.lo[i] = wl4[i];
  }
  split_batch_kernel<<<dim3(WSZ / 4 / 256, 4), 256>>>(wsb, WSZ / 4);

  SplitBatch asb = {};
  asb.src[0] = queries; asb.src[1] = keys; asb.src[2] = values;
  for (int i = 0; i < 3; i++) {
    asb.hi[i] = xh + i * XSZ;
    asb.lo[i] = xl + i * XSZ;
  }
  split_batch_kernel<<<dim3(XSZ / 4 / 256, 3), 256>>>(asb, XSZ / 4);

  // --- Q/K/V projections in one batched launch (grid.z = 3) ---
  GemmBatch gp = {};
  for (int i = 0; i < 3; i++) {
    gp.ah[i] = xh + i * XSZ;
    gp.al[i] = xl + i * XSZ;
    gp.wh[i] = wh[i];
    gp.wl[i] = wl4[i];
  }
  gp.ch[0] = qh; gp.cl[0] = ql;
  gp.ch[1] = kh; gp.cl[1] = kl;
  gp.ch[2] = vh; gp.cl[2] = vl;
  gemm_tc_hmma<true><<<dim3(HID / 128, M / 128, 3), 256, GEMM_SMEM>>>(gp,
                                                                      nullptr);

  // --- attention ---
  attn_hmma<<<dim3(S / 128, NH, B), 256, ATTN_SMEM>>>(qh, ql, kh, kl, vh, vl,
                                                      vlens, oh, ol);

  // --- output projection (fp32 out) ---
  GemmBatch go = {};
  go.ah[0] = oh; go.al[0] = ol;
  go.wh[0] = wh[3]; go.wl[0] = wl4[3];
  gemm_tc_hmma<false><<<dim3(HID / 128, M / 128, 1), 256, GEMM_SMEM>>>(go,
                                                                       out);
}

// round 7
// speedup vs baseline: 1.1269x; 1.1269x over previous
#include <cuda_runtime.h>
#include <cuda_bf16.h>
#include <cstdint>

// Problem constants
constexpr int B   = 4;
constexpr int S   = 2048;
constexpr int HID = 512;
constexpr int NH  = 8;
constexpr int DH  = 64;
constexpr int M   = B * S;       // 8192

// Scratch (device globals — no runtime allocation allowed)
__device__ __nv_bfloat16 g_wh[HID * HID], g_wl[HID * HID];
__device__ __nv_bfloat16 g_qh[M * HID], g_ql[M * HID];
__device__ __nv_bfloat16 g_kh[M * HID], g_kl[M * HID];
__device__ __nv_bfloat16 g_vh[M * HID], g_vl[M * HID];
__device__ __nv_bfloat16 g_oh[M * HID], g_ol[M * HID];

// ---------------------------------------------------------------------------
// mma.sync / ldmatrix / cp.async helpers (plain sm_80+ PTX)
// ---------------------------------------------------------------------------
__device__ __forceinline__ uint32_t smem_u32(const void* p) {
  uint32_t a;
  asm("{ .reg .u64 t; cvta.to.shared.u64 t, %1; cvt.u32.u64 %0, t; }"
      : "=r"(a) : "l"(p));
  return a;
}

#define LDMX4(r0, r1, r2, r3, addr)                                       \
  asm volatile(                                                           \
      "ldmatrix.sync.aligned.m8n8.x4.shared.b16 {%0,%1,%2,%3}, [%4];"     \
      : "=r"(r0), "=r"(r1), "=r"(r2), "=r"(r3) : "r"(addr))

#define LDMX4T(r0, r1, r2, r3, addr)                                      \
  asm volatile(                                                           \
      "ldmatrix.sync.aligned.m8n8.x4.trans.shared.b16 {%0,%1,%2,%3}, [%4];" \
      : "=r"(r0), "=r"(r1), "=r"(r2), "=r"(r3) : "r"(addr))

#define CP_ASYNC16(dst, src)                                              \
  asm volatile("cp.async.cg.shared.global [%0], [%1], 16;" ::             \
                   "r"(dst), "l"(src))
#define CP_COMMIT() asm volatile("cp.async.commit_group;" ::: "memory")
#define CP_WAIT0() asm volatile("cp.async.wait_group 0;" ::: "memory")

__device__ __forceinline__ void mma_bf16(float& c0, float& c1, float& c2,
                                         float& c3, uint32_t a0, uint32_t a1,
                                         uint32_t a2, uint32_t a3,
                                         uint32_t b0, uint32_t b1) {
  asm volatile(
      "mma.sync.aligned.m16n8k16.row.col.f32.bf16.bf16.f32 "
      "{%0,%1,%2,%3}, {%4,%5,%6,%7}, {%8,%9}, {%0,%1,%2,%3};"
      : "+f"(c0), "+f"(c1), "+f"(c2), "+f"(c3)
      : "r"(a0), "r"(a1), "r"(a2), "r"(a3), "r"(b0), "r"(b1));
}

__device__ __forceinline__ uint32_t pack_bf16(float a, float b) {
  __nv_bfloat162 t = __floats2bfloat162_rn(a, b);
  return *(uint32_t*)&t;
}

// ---------------------------------------------------------------------------
// fp32 -> (bf16 hi, bf16 lo) split (weights only).
// ---------------------------------------------------------------------------
__global__ __launch_bounds__(256) void split_kernel(
    const float* __restrict__ x, __nv_bfloat16* __restrict__ hi,
    __nv_bfloat16* __restrict__ lo, int n4) {
  int i = blockIdx.x * blockDim.x + threadIdx.x;
  if (i >= n4) return;
  float4 v = ((const float4*)x)[i];
  float hx = __bfloat162float(__float2bfloat16(v.x));
  float hy = __bfloat162float(__float2bfloat16(v.y));
  float hz = __bfloat162float(__float2bfloat16(v.z));
  float hw = __bfloat162float(__float2bfloat16(v.w));
  uint2 ho, lw;
  ho.x = pack_bf16(v.x, v.y);
  ho.y = pack_bf16(v.z, v.w);
  lw.x = pack_bf16(v.x - hx, v.y - hy);
  lw.y = pack_bf16(v.z - hz, v.w - hw);
  ((uint2*)hi)[i] = ho;
  ((uint2*)lo)[i] = lw;
}

// ---------------------------------------------------------------------------
// HMMA bf16x3 GEMM-NT: C[M,512] = A @ W^T with fp32-equivalent accuracy.
// CTA 128x128, 8 warps, warp 64x32 (4x4 m16n8k16). K chunks of 64.
// AFP32: A read as fp32, hi/lo conversion fused into the smem-store path.
// SPLIT: emit bf16 hi/lo instead of fp32.
// (round-5 structure: best measured GEMM; round-6 pipeline regressed)
// ---------------------------------------------------------------------------
constexpr int RS = 72;                    // smem row stride in bf16 (144 B)
constexpr int TILE_BYTES = 128 * RS * 2;  // 18432 per tile
constexpr int SA_H = 0;
constexpr int SA_L = SA_H + TILE_BYTES;
constexpr int SW_H = SA_L + TILE_BYTES;
constexpr int SW_L = SW_H + TILE_BYTES;
constexpr int GEMM_SMEM = SW_L + TILE_BYTES;  // 73728 B

template <bool AFP32, bool SPLIT>
__global__ __launch_bounds__(256, 2) void gemm_tc_hmma(
    const float* __restrict__ Af, const __nv_bfloat16* __restrict__ Ah,
    const __nv_bfloat16* __restrict__ Al, const __nv_bfloat16* __restrict__ Wh,
    const __nv_bfloat16* __restrict__ Wl, float* __restrict__ C,
    __nv_bfloat16* __restrict__ Ch, __nv_bfloat16* __restrict__ Cl) {
  extern __shared__ __align__(128) char smem[];
  const uint32_t sb = smem_u32(smem);
  const int t = threadIdx.x;
  const int wid = t >> 5, l = t & 31;
  const int wm = wid >> 2;
  const int wn = wid & 3;
  const int m0 = blockIdx.y * 128;
  const int n0 = blockIdx.x * 128;

  float acc[4][4][4] = {};

  const int a_row = (l & 15);
  const int a_koff = ((l >> 4) & 1) * 16;
  const int b_row = (l & 7) + ((l >> 4) & 1) * 8;
  const int b_koff = ((l >> 3) & 1) * 16;

  for (int kc = 0; kc < 8; kc++) {
    const int koff = kc * 64;
    __syncthreads();
    // --- A tiles ---
    if constexpr (AFP32) {
#pragma unroll
      for (int i = 0; i < 8; i++) {     // 2048 float4
        int v = t + i * 256;
        int row = v >> 4, c = v & 15;
        float4 fv = *(const float4*)(Af + (size_t)(m0 + row) * HID + koff +
                                     c * 4);
        float hx = __bfloat162float(__float2bfloat16(fv.x));
        float hy = __bfloat162float(__float2bfloat16(fv.y));
        float hz = __bfloat162float(__float2bfloat16(fv.z));
        float hw = __bfloat162float(__float2bfloat16(fv.w));
        uint2 ho, lw;
        ho.x = pack_bf16(fv.x, fv.y);
        ho.y = pack_bf16(fv.z, fv.w);
        lw.x = pack_bf16(fv.x - hx, fv.y - hy);
        lw.y = pack_bf16(fv.z - hz, fv.w - hw);
        uint32_t so = row * (RS * 2) + c * 8;
        *(uint2*)(smem + SA_H + so) = ho;
        *(uint2*)(smem + SA_L + so) = lw;
      }
    } else {
#pragma unroll
      for (int i = 0; i < 4; i++) {
        int v = t + i * 256;
        int row = v >> 3, c = v & 7;
        size_t ga = (size_t)(m0 + row) * HID + koff + c * 8;
        uint32_t so = row * (RS * 2) + c * 16;
        *(uint4*)(smem + SA_H + so) = *(const uint4*)(Ah + ga);
        *(uint4*)(smem + SA_L + so) = *(const uint4*)(Al + ga);
      }
    }
    // --- W tiles ---
#pragma unroll
    for (int i = 0; i < 4; i++) {
      int v = t + i * 256;
      int row = v >> 3, c = v & 7;
      size_t gw = (size_t)(n0 + row) * HID + koff + c * 8;
      uint32_t so = row * (RS * 2) + c * 16;
      *(uint4*)(smem + SW_H + so) = *(const uint4*)(Wh + gw);
      *(uint4*)(smem + SW_L + so) = *(const uint4*)(Wl + gw);
    }
    __syncthreads();

#pragma unroll
    for (int ks = 0; ks < 4; ks++) {
      const int kb = ks * 32;
      uint32_t ah[4][4], al[4][4], bh[8], bl[8];
#pragma unroll
      for (int mt = 0; mt < 4; mt++) {
        uint32_t ra = (wm * 64 + mt * 16 + a_row) * (RS * 2) + kb + a_koff;
        LDMX4(ah[mt][0], ah[mt][1], ah[mt][2], ah[mt][3], sb + SA_H + ra);
        LDMX4(al[mt][0], al[mt][1], al[mt][2], al[mt][3], sb + SA_L + ra);
      }
#pragma unroll
      for (int np = 0; np < 2; np++) {
        uint32_t rb = (wn * 32 + np * 16 + b_row) * (RS * 2) + kb + b_koff;
        LDMX4(bh[np * 4 + 0], bh[np * 4 + 1], bh[np * 4 + 2], bh[np * 4 + 3],
              sb + SW_H + rb);
        LDMX4(bl[np * 4 + 0], bl[np * 4 + 1], bl[np * 4 + 2], bl[np * 4 + 3],
              sb + SW_L + rb);
      }
#pragma unroll
      for (int mt = 0; mt < 4; mt++)
#pragma unroll
        for (int nt = 0; nt < 4; nt++) {
          float* c = acc[mt][nt];
          mma_bf16(c[0], c[1], c[2], c[3], ah[mt][0], ah[mt][1], ah[mt][2],
                   ah[mt][3], bh[nt * 2], bh[nt * 2 + 1]);
          mma_bf16(c[0], c[1], c[2], c[3], ah[mt][0], ah[mt][1], ah[mt][2],
                   ah[mt][3], bl[nt * 2], bl[nt * 2 + 1]);
          mma_bf16(c[0], c[1], c[2], c[3], al[mt][0], al[mt][1], al[mt][2],
                   al[mt][3], bh[nt * 2], bh[nt * 2 + 1]);
        }
    }
  }

  const int er = l >> 2, ec = (l & 3) * 2;
#pragma unroll
  for (int mt = 0; mt < 4; mt++) {
    int row = m0 + wm * 64 + mt * 16 + er;
#pragma unroll
    for (int nt = 0; nt < 4; nt++) {
      int col = n0 + wn * 32 + nt * 8 + ec;
      float* a = acc[mt][nt];
      if constexpr (SPLIT) {
        float h0 = __bfloat162float(__float2bfloat16(a[0]));
        float h1 = __bfloat162float(__float2bfloat16(a[1]));
        float h2 = __bfloat162float(__float2bfloat16(a[2]));
        float h3 = __bfloat162float(__float2bfloat16(a[3]));
        size_t i0 = (size_t)row * HID + col;
        size_t i1 = (size_t)(row + 8) * HID + col;
        *(uint32_t*)&Ch[i0] = pack_bf16(a[0], a[1]);
        *(uint32_t*)&Cl[i0] = pack_bf16(a[0] - h0, a[1] - h1);
        *(uint32_t*)&Ch[i1] = pack_bf16(a[2], a[3]);
        *(uint32_t*)&Cl[i1] = pack_bf16(a[2] - h2, a[3] - h3);
      } else {
        *(float2*)&C[(size_t)row * HID + col] = make_float2(a[0], a[1]);
        *(float2*)&C[(size_t)(row + 8) * HID + col] = make_float2(a[2], a[3]);
      }
    }
  }
}

// ---------------------------------------------------------------------------
// HMMA flash attention (bf16x3, fp32 softmax). CTA: 128 q x one (b,h).
// 8 warps x 16 q-rows, kv tiles of 64. 2-stage cp.async for K/V; V fragments
// via ldmatrix.trans. __launch_bounds__(256,2): cap regs at 128 so TWO CTAs
// fit per SM (round-6 ncu: regs=138 -> reg-limited to 1 CTA, occ 12.5%,
// tensor 49% — softmax chains stall the tensor pipe with nothing to overlap).
// ---------------------------------------------------------------------------
constexpr int AQ_H = 0;                        // Q hi: 128 x 144B
constexpr int AQ_L = 128 * RS * 2;             // 18432
constexpr int STG0 = 2 * 128 * RS * 2;         // 36864
constexpr int KV_COMP = 64 * RS * 2;           // 9216 per component
constexpr int STG_SZ = 4 * KV_COMP;            // 36864
constexpr int ATTN_SMEM = STG0 + 2 * STG_SZ;   // 110592 (x2 = 216KB < 228KB)

__global__ __launch_bounds__(256, 2) void attn_hmma(
    const __nv_bfloat16* __restrict__ Qh, const __nv_bfloat16* __restrict__ Ql,
    const __nv_bfloat16* __restrict__ Kh, const __nv_bfloat16* __restrict__ Kl,
    const __nv_bfloat16* __restrict__ Vh, const __nv_bfloat16* __restrict__ Vl,
    const int* __restrict__ valid_lens, __nv_bfloat16* __restrict__ Oh,
    __nv_bfloat16* __restrict__ Ol) {
  extern __shared__ __align__(128) char smem[];
  const uint32_t sb = smem_u32(smem);
  const int qt = blockIdx.x, h = blockIdx.y, b = blockIdx.z;
  const int t = threadIdx.x;
  const int wid = t >> 5, l = t & 31;
  const int q0 = qt * 128;
  const int vlen = valid_lens[b];
  const int ntiles = (vlen + 63) >> 6;

  const __nv_bfloat16* kv_src[4] = {Kh, Kl, Vh, Vl};

  auto issue_tile = [&](int stage, int kbase) {
#pragma unroll
    for (int i = 0; i < 8; i++) {
      int idx = t + i * 256;
      int comp = idx >> 9;
      int r = (idx >> 3) & 63;
      int c = idx & 7;
      const __nv_bfloat16* src =
          kv_src[comp] + (size_t)(b * S + kbase + r) * HID + h * DH + c * 8;
      uint32_t dst =
          sb + STG0 + stage * STG_SZ + comp * KV_COMP + r * (RS * 2) + c * 16;
      CP_ASYNC16(dst, src);
    }
  };

  issue_tile(0, 0);
  CP_COMMIT();
#pragma unroll
  for (int i = 0; i < 4; i++) {
    int v = t + i * 256;
    int row = v >> 3, c = v & 7;
    size_t g = (size_t)(b * S + q0 + row) * HID + h * DH + c * 8;
    uint32_t so = row * (RS * 2) + c * 16;
    *(uint4*)(smem + AQ_H + so) = *(const uint4*)(Qh + g);
    *(uint4*)(smem + AQ_L + so) = *(const uint4*)(Ql + g);
  }
  __syncthreads();

  const int a_row = (l & 15);
  const int a_koff = ((l >> 4) & 1) * 16;
  const int b_row = (l & 7) + ((l >> 4) & 1) * 8;
  const int b_koff = ((l >> 3) & 1) * 16;
  const int v_row = (l & 7) + ((l >> 3) & 1) * 8;
  const int v_col = ((l >> 4) & 1) * 16;
  const int cb = (l & 3) * 2;

  uint32_t qh[4][4], ql[4][4];
#pragma unroll
  for (int ks = 0; ks < 4; ks++) {
    uint32_t ra = (wid * 16 + a_row) * (RS * 2) + ks * 32 + a_koff;
    LDMX4(qh[ks][0], qh[ks][1], qh[ks][2], qh[ks][3], sb + AQ_H + ra);
    LDMX4(ql[ks][0], ql[ks][1], ql[ks][2], ql[ks][3], sb + AQ_L + ra);
  }

  float oacc[8][4] = {};
  float m0r = -1e30f, m1r = -1e30f, l0r = 0.f, l1r = 0.f;

  for (int kt = 0; kt < ntiles; kt++) {
    const int kbase = kt * 64;
    const uint32_t kb_h = sb + STG0 + (kt & 1) * STG_SZ;
    const uint32_t kb_l = kb_h + KV_COMP;
    const uint32_t vb_h = kb_h + 2 * KV_COMP;
    const uint32_t vb_l = kb_h + 3 * KV_COMP;

    CP_WAIT0();
    __syncthreads();
    if (kt + 1 < ntiles) {
      issue_tile((kt + 1) & 1, kbase + 64);
      CP_COMMIT();
    }

    float sc[8][4];
#pragma unroll
    for (int nt = 0; nt < 8; nt++)
#pragma unroll
      for (int c = 0; c < 4; c++) sc[nt][c] = 0.f;
#pragma unroll
    for (int ks = 0; ks < 4; ks++) {
      uint32_t khf[16], klf[16];
#pragma unroll
      for (int np = 0; np < 4; np++) {
        uint32_t rb = (np * 16 + b_row) * (RS * 2) + ks * 32 + b_koff;
        LDMX4(khf[np * 4 + 0], khf[np * 4 + 1], khf[np * 4 + 2],
              khf[np * 4 + 3], kb_h + rb);
        LDMX4(klf[np * 4 + 0], klf[np * 4 + 1], klf[np * 4 + 2],
              klf[np * 4 + 3], kb_l + rb);
      }
#pragma unroll
      for (int nt = 0; nt < 8; nt++) {
        float* c = sc[nt];
        mma_bf16(c[0], c[1], c[2], c[3], qh[ks][0], qh[ks][1], qh[ks][2],
                 qh[ks][3], khf[nt * 2], khf[nt * 2 + 1]);
        mma_bf16(c[0], c[1], c[2], c[3], qh[ks][0], qh[ks][1], qh[ks][2],
                 qh[ks][3], klf[nt * 2], klf[nt * 2 + 1]);
        mma_bf16(c[0], c[1], c[2], c[3], ql[ks][0], ql[ks][1], ql[ks][2],
                 ql[ks][3], khf[nt * 2], khf[nt * 2 + 1]);
      }
    }

#pragma unroll
    for (int nt = 0; nt < 8; nt++)
#pragma unroll
      for (int c = 0; c < 4; c++) sc[nt][c] *= 0.125f;
    if (kbase + 64 > vlen) {
#pragma unroll
      for (int nt = 0; nt < 8; nt++) {
        int k0 = kbase + nt * 8 + cb;
        if (k0 >= vlen) { sc[nt][0] = -1e30f; sc[nt][2] = -1e30f; }
        if (k0 + 1 >= vlen) { sc[nt][1] = -1e30f; sc[nt][3] = -1e30f; }
      }
    }

    float rm0 = -1e30f, rm1 = -1e30f;
#pragma unroll
    for (int nt = 0; nt < 8; nt++) {
      rm0 = fmaxf(rm0, fmaxf(sc[nt][0], sc[nt][1]));
      rm1 = fmaxf(rm1, fmaxf(sc[nt][2], sc[nt][3]));
    }
    rm0 = fmaxf(rm0, __shfl_xor_sync(0xffffffffu, rm0, 1));
    rm0 = fmaxf(rm0, __shfl_xor_sync(0xffffffffu, rm0, 2));
    rm1 = fmaxf(rm1, __shfl_xor_sync(0xffffffffu, rm1, 1));
    rm1 = fmaxf(rm1, __shfl_xor_sync(0xffffffffu, rm1, 2));
    float mn0 = fmaxf(m0r, rm0), mn1 = fmaxf(m1r, rm1);
    float corr0 = __expf(m0r - mn0), corr1 = __expf(m1r - mn1);

    uint32_t ph[8][2], pl[8][2];
    float rs0 = 0.f, rs1 = 0.f;
#pragma unroll
    for (int nt = 0; nt < 8; nt++) {
      float p0 = __expf(sc[nt][0] - mn0);
      float p1 = __expf(sc[nt][1] - mn0);
      float p2 = __expf(sc[nt][2] - mn1);
      float p3 = __expf(sc[nt][3] - mn1);
      rs0 += p0 + p1;
      rs1 += p2 + p3;
      float h0 = __bfloat162float(__float2bfloat16(p0));
      float h1 = __bfloat162float(__float2bfloat16(p1));
      float h2 = __bfloat162float(__float2bfloat16(p2));
      float h3 = __bfloat162float(__float2bfloat16(p3));
      ph[nt][0] = pack_bf16(p0, p1);
      ph[nt][1] = pack_bf16(p2, p3);
      pl[nt][0] = pack_bf16(p0 - h0, p1 - h1);
      pl[nt][1] = pack_bf16(p2 - h2, p3 - h3);
    }
    rs0 += __shfl_xor_sync(0xffffffffu, rs0, 1);
    rs0 += __shfl_xor_sync(0xffffffffu, rs0, 2);
    rs1 += __shfl_xor_sync(0xffffffffu, rs1, 1);
    rs1 += __shfl_xor_sync(0xffffffffu, rs1, 2);
    l0r = l0r * corr0 + rs0;
    l1r = l1r * corr1 + rs1;
    m0r = mn0;
    m1r = mn1;
#pragma unroll
    for (int nt = 0; nt < 8; nt++) {
      oacc[nt][0] *= corr0;
      oacc[nt][1] *= corr0;
      oacc[nt][2] *= corr1;
      oacc[nt][3] *= corr1;
    }

#pragma unroll
    for (int ks = 0; ks < 4; ks++) {
      uint32_t vhf[16], vlf[16];
#pragma unroll
      for (int np = 0; np < 4; np++) {
        uint32_t rv = (ks * 16 + v_row) * (RS * 2) + np * 32 + v_col;
        LDMX4T(vhf[np * 4 + 0], vhf[np * 4 + 1], vhf[np * 4 + 2],
               vhf[np * 4 + 3], vb_h + rv);
        LDMX4T(vlf[np * 4 + 0], vlf[np * 4 + 1], vlf[np * 4 + 2],
               vlf[np * 4 + 3], vb_l + rv);
      }
      uint32_t a0 = ph[2 * ks][0], a1 = ph[2 * ks][1];
      uint32_t a2 = ph[2 * ks + 1][0], a3 = ph[2 * ks + 1][1];
      uint32_t e0 = pl[2 * ks][0], e1 = pl[2 * ks][1];
      uint32_t e2 = pl[2 * ks + 1][0], e3 = pl[2 * ks + 1][1];
#pragma unroll
      for (int nt = 0; nt < 8; nt++) {
        float* c = oacc[nt];
        mma_bf16(c[0], c[1], c[2], c[3], a0, a1, a2, a3, vhf[nt * 2],
                 vhf[nt * 2 + 1]);
        mma_bf16(c[0], c[1], c[2], c[3], a0, a1, a2, a3, vlf[nt * 2],
                 vlf[nt * 2 + 1]);
        mma_bf16(c[0], c[1], c[2], c[3], e0, e1, e2, e3, vhf[nt * 2],
                 vhf[nt * 2 + 1]);
      }
    }
  }

  float inv0 = 1.f / l0r, inv1 = 1.f / l1r;
  int r0 = q0 + wid * 16 + (l >> 2);
#pragma unroll
  for (int nt = 0; nt < 8; nt++) {
    int col = h * DH + nt * 8 + cb;
    float o0 = oacc[nt][0] * inv0, o1 = oacc[nt][1] * inv0;
    float o2 = oacc[nt][2] * inv1, o3 = oacc[nt][3] * inv1;
    float h0 = __bfloat162float(__float2bfloat16(o0));
    float h1 = __bfloat162float(__float2bfloat16(o1));
    float h2 = __bfloat162float(__float2bfloat16(o2));
    float h3 = __bfloat162float(__float2bfloat16(o3));
    size_t i0 = (size_t)(b * S + r0) * HID + col;
    size_t i1 = (size_t)(b * S + r0 + 8) * HID + col;
    *(uint32_t*)&Oh[i0] = pack_bf16(o0, o1);
    *(uint32_t*)&Ol[i0] = pack_bf16(o0 - h0, o1 - h1);
    *(uint32_t*)&Oh[i1] = pack_bf16(o2, o3);
    *(uint32_t*)&Ol[i1] = pack_bf16(o2 - h2, o3 - h3);
  }
}

// ---------------------------------------------------------------------------
extern "C" void kernel_launch(void* const* d_in, const int* in_sizes, int n_in,
                              void* d_out, int out_size) {
  const float* queries = (const float*)d_in[0];
  const float* keys    = (const float*)d_in[1];
  const float* values  = (const float*)d_in[2];
  const int*   vlens   = (const int*)d_in[3];
  const float* Wq      = (const float*)d_in[4];
  const float* Wk      = (const float*)d_in[5];
  const float* Wv      = (const float*)d_in[6];
  const float* Wo      = (const float*)d_in[7];
  float* out = (float*)d_out;

  __nv_bfloat16 *wh, *wl, *qh, *ql, *kh, *kl, *vh, *vl, *oh, *ol;
  cudaGetSymbolAddress((void**)&wh, g_wh);
  cudaGetSymbolAddress((void**)&wl, g_wl);
  cudaGetSymbolAddress((void**)&qh, g_qh);
  cudaGetSymbolAddress((void**)&ql, g_ql);
  cudaGetSymbolAddress((void**)&kh, g_kh);
  cudaGetSymbolAddress((void**)&kl, g_kl);
  cudaGetSymbolAddress((void**)&vh, g_vh);
  cudaGetSymbolAddress((void**)&vl, g_vl);
  cudaGetSymbolAddress((void**)&oh, g_oh);
  cudaGetSymbolAddress((void**)&ol, g_ol);

  cudaFuncSetAttribute(gemm_tc_hmma<true, true>,
                       cudaFuncAttributeMaxDynamicSharedMemorySize, GEMM_SMEM);
  cudaFuncSetAttribute(gemm_tc_hmma<false, false>,
                       cudaFuncAttributeMaxDynamicSharedMemorySize, GEMM_SMEM);
  cudaFuncSetAttribute(attn_hmma,
                       cudaFuncAttributeMaxDynamicSharedMemorySize, ATTN_SMEM);

  const int w_n4 = HID * HID / 4;
  dim3 gemm_grid(HID / 128, M / 128);  // (4, 64)

  // Q/K/V projections: A fp32 conversion fused; emit bf16 hi/lo
  split_kernel<<<w_n4 / 256, 256>>>(Wq, wh, wl, w_n4);
  gemm_tc_hmma<true, true><<<gemm_grid, 256, GEMM_SMEM>>>(
      queries, nullptr, nullptr, wh, wl, nullptr, qh, ql);
  split_kernel<<<w_n4 / 256, 256>>>(Wk, wh, wl, w_n4);
  gemm_tc_hmma<true, true><<<gemm_grid, 256, GEMM_SMEM>>>(
      keys, nullptr, nullptr, wh, wl, nullptr, kh, kl);
  split_kernel<<<w_n4 / 256, 256>>>(Wv, wh, wl, w_n4);
  gemm_tc_hmma<true, true><<<gemm_grid, 256, GEMM_SMEM>>>(
      values, nullptr, nullptr, wh, wl, nullptr, vh, vl);

  // attention
  attn_hmma<<<dim3(S / 128, NH, B), 256, ATTN_SMEM>>>(qh, ql, kh, kl, vh, vl,
                                                      vlens, oh, ol);

  // output projection (bf16 hi/lo A, fp32 out)
  split_kernel<<<w_n4 / 256, 256>>>(Wo, wh, wl, w_n4);
  gemm_tc_hmma<false, false><<<gemm_grid, 256, GEMM_SMEM>>>(
      nullptr, oh, ol, wh, wl, out, nullptr, nullptr);
}

// round 8
// speedup vs baseline: 1.1756x; 1.0432x over previous
#include <cuda_runtime.h>
#include <cuda_bf16.h>
#include <cstdint>

// Problem constants
constexpr int B   = 4;
constexpr int S   = 2048;
constexpr int HID = 512;
constexpr int NH  = 8;
constexpr int DH  = 64;
constexpr int M   = B * S;       // 8192

// Scratch (device globals — no runtime allocation allowed)
__device__ __nv_bfloat16 g_wh[4][HID * HID], g_wl[4][HID * HID];
__device__ __nv_bfloat16 g_qh[M * HID], g_ql[M * HID];
__device__ __nv_bfloat16 g_kh[M * HID], g_kl[M * HID];
__device__ __nv_bfloat16 g_vh[M * HID], g_vl[M * HID];
__device__ __nv_bfloat16 g_oh[M * HID], g_ol[M * HID];

// ---------------------------------------------------------------------------
// mma.sync / ldmatrix / cp.async helpers (plain sm_80+ PTX)
// ---------------------------------------------------------------------------
__device__ __forceinline__ uint32_t smem_u32(const void* p) {
  uint32_t a;
  asm("{ .reg .u64 t; cvta.to.shared.u64 t, %1; cvt.u32.u64 %0, t; }"
      : "=r"(a) : "l"(p));
  return a;
}

#define LDMX4(r0, r1, r2, r3, addr)                                       \
  asm volatile(                                                           \
      "ldmatrix.sync.aligned.m8n8.x4.shared.b16 {%0,%1,%2,%3}, [%4];"     \
      : "=r"(r0), "=r"(r1), "=r"(r2), "=r"(r3) : "r"(addr))

#define LDMX4T(r0, r1, r2, r3, addr)                                      \
  asm volatile(                                                           \
      "ldmatrix.sync.aligned.m8n8.x4.trans.shared.b16 {%0,%1,%2,%3}, [%4];" \
      : "=r"(r0), "=r"(r1), "=r"(r2), "=r"(r3) : "r"(addr))

#define CP_ASYNC16(dst, src)                                              \
  asm volatile("cp.async.cg.shared.global [%0], [%1], 16;" ::             \
                   "r"(dst), "l"(src))
#define CP_COMMIT() asm volatile("cp.async.commit_group;" ::: "memory")
#define CP_WAIT0() asm volatile("cp.async.wait_group 0;" ::: "memory")

__device__ __forceinline__ void mma_bf16(float& c0, float& c1, float& c2,
                                         float& c3, uint32_t a0, uint32_t a1,
                                         uint32_t a2, uint32_t a3,
                                         uint32_t b0, uint32_t b1) {
  asm volatile(
      "mma.sync.aligned.m16n8k16.row.col.f32.bf16.bf16.f32 "
      "{%0,%1,%2,%3}, {%4,%5,%6,%7}, {%8,%9}, {%0,%1,%2,%3};"
      : "+f"(c0), "+f"(c1), "+f"(c2), "+f"(c3)
      : "r"(a0), "r"(a1), "r"(a2), "r"(a3), "r"(b0), "r"(b1));
}

__device__ __forceinline__ uint32_t pack_bf16(float a, float b) {
  __nv_bfloat162 t = __floats2bfloat162_rn(a, b);
  return *(uint32_t*)&t;
}

// ---------------------------------------------------------------------------
// fp32 -> (bf16 hi, bf16 lo) split, batched over blockIdx.y (weights).
// ---------------------------------------------------------------------------
struct SplitBatch {
  const float* src[4];
  __nv_bfloat16* hi[4];
  __nv_bfloat16* lo[4];
};

__global__ __launch_bounds__(256) void split_batch_kernel(SplitBatch sb,
                                                          int n4) {
  int i = blockIdx.x * blockDim.x + threadIdx.x;
  if (i >= n4) return;
  int z = blockIdx.y;
  float4 v = ((const float4*)sb.src[z])[i];
  float hx = __bfloat162float(__float2bfloat16(v.x));
  float hy = __bfloat162float(__float2bfloat16(v.y));
  float hz = __bfloat162float(__float2bfloat16(v.z));
  float hw = __bfloat162float(__float2bfloat16(v.w));
  uint2 ho, lw;
  ho.x = pack_bf16(v.x, v.y);
  ho.y = pack_bf16(v.z, v.w);
  lw.x = pack_bf16(v.x - hx, v.y - hy);
  lw.y = pack_bf16(v.z - hz, v.w - hw);
  ((uint2*)sb.hi[z])[i] = ho;
  ((uint2*)sb.lo[z])[i] = lw;
}

// ---------------------------------------------------------------------------
// HMMA bf16x3 GEMM-NT: C = A @ W^T with fp32-equivalent accuracy.
// CTA 128x128, 8 warps, warp 64x32 (4x4 m16n8k16). K chunks of 64,
// single-buffered (round-5 internals: fastest measured variant).
// AFP32: A read as fp32 from p.af[z], hi/lo conversion fused into smem store.
// SPLIT: emit bf16 hi/lo (p.ch[z]/p.cl[z]); else fp32 to p.c.
// grid.z batches independent GEMMs into ONE launch — a single (4,64) launch
// is 256 CTAs on 296 occupancy slots: 40 SMs idle half the launch.
// ---------------------------------------------------------------------------
constexpr int RS = 72;                    // smem row stride in bf16 (144 B)
constexpr int TILE_BYTES = 128 * RS * 2;  // 18432 per tile
constexpr int SA_H = 0;
constexpr int SA_L = SA_H + TILE_BYTES;
constexpr int SW_H = SA_L + TILE_BYTES;
constexpr int SW_L = SW_H + TILE_BYTES;
constexpr int GEMM_SMEM = SW_L + TILE_BYTES;  // 73728 B

struct GemmBatch {
  const float* af[3];                 // AFP32 inputs
  const __nv_bfloat16* ah;            // !AFP32 input (out-proj)
  const __nv_bfloat16* al;
  const __nv_bfloat16* wh[3];
  const __nv_bfloat16* wl[3];
  __nv_bfloat16* ch[3];               // SPLIT outputs
  __nv_bfloat16* cl[3];
  float* c;                           // !SPLIT output
};

template <bool AFP32, bool SPLIT>
__global__ __launch_bounds__(256, 2) void gemm_tc_hmma(GemmBatch p) {
  extern __shared__ __align__(128) char smem[];
  const uint32_t sb = smem_u32(smem);
  const int t = threadIdx.x;
  const int wid = t >> 5, l = t & 31;
  const int wm = wid >> 2;
  const int wn = wid & 3;
  const int m0 = blockIdx.y * 128;
  const int n0 = blockIdx.x * 128;
  const int z = blockIdx.z;

  const __nv_bfloat16* Wh = p.wh[z];
  const __nv_bfloat16* Wl = p.wl[z];

  float acc[4][4][4] = {};

  const int a_row = (l & 15);
  const int a_koff = ((l >> 4) & 1) * 16;
  const int b_row = (l & 7) + ((l >> 4) & 1) * 8;
  const int b_koff = ((l >> 3) & 1) * 16;

  for (int kc = 0; kc < 8; kc++) {
    const int koff = kc * 64;
    __syncthreads();
    // --- A tiles ---
    if constexpr (AFP32) {
      const float* Af = p.af[z];
#pragma unroll
      for (int i = 0; i < 8; i++) {     // 2048 float4
        int v = t + i * 256;
        int row = v >> 4, c = v & 15;
        float4 fv = *(const float4*)(Af + (size_t)(m0 + row) * HID + koff +
                                     c * 4);
        float hx = __bfloat162float(__float2bfloat16(fv.x));
        float hy = __bfloat162float(__float2bfloat16(fv.y));
        float hz = __bfloat162float(__float2bfloat16(fv.z));
        float hw = __bfloat162float(__float2bfloat16(fv.w));
        uint2 ho, lw;
        ho.x = pack_bf16(fv.x, fv.y);
        ho.y = pack_bf16(fv.z, fv.w);
        lw.x = pack_bf16(fv.x - hx, fv.y - hy);
        lw.y = pack_bf16(fv.z - hz, fv.w - hw);
        uint32_t so = row * (RS * 2) + c * 8;
        *(uint2*)(smem + SA_H + so) = ho;
        *(uint2*)(smem + SA_L + so) = lw;
      }
    } else {
#pragma unroll
      for (int i = 0; i < 4; i++) {
        int v = t + i * 256;
        int row = v >> 3, c = v & 7;
        size_t ga = (size_t)(m0 + row) * HID + koff + c * 8;
        uint32_t so = row * (RS * 2) + c * 16;
        *(uint4*)(smem + SA_H + so) = *(const uint4*)(p.ah + ga);
        *(uint4*)(smem + SA_L + so) = *(const uint4*)(p.al + ga);
      }
    }
    // --- W tiles ---
#pragma unroll
    for (int i = 0; i < 4; i++) {
      int v = t + i * 256;
      int row = v >> 3, c = v & 7;
      size_t gw = (size_t)(n0 + row) * HID + koff + c * 8;
      uint32_t so = row * (RS * 2) + c * 16;
      *(uint4*)(smem + SW_H + so) = *(const uint4*)(Wh + gw);
      *(uint4*)(smem + SW_L + so) = *(const uint4*)(Wl + gw);
    }
    __syncthreads();

#pragma unroll
    for (int ks = 0; ks < 4; ks++) {
      const int kb = ks * 32;
      uint32_t ah[4][4], al[4][4], bh[8], bl[8];
#pragma unroll
      for (int mt = 0; mt < 4; mt++) {
        uint32_t ra = (wm * 64 + mt * 16 + a_row) * (RS * 2) + kb + a_koff;
        LDMX4(ah[mt][0], ah[mt][1], ah[mt][2], ah[mt][3], sb + SA_H + ra);
        LDMX4(al[mt][0], al[mt][1], al[mt][2], al[mt][3], sb + SA_L + ra);
      }
#pragma unroll
      for (int np = 0; np < 2; np++) {
        uint32_t rb = (wn * 32 + np * 16 + b_row) * (RS * 2) + kb + b_koff;
        LDMX4(bh[np * 4 + 0], bh[np * 4 + 1], bh[np * 4 + 2], bh[np * 4 + 3],
              sb + SW_H + rb);
        LDMX4(bl[np * 4 + 0], bl[np * 4 + 1], bl[np * 4 + 2], bl[np * 4 + 3],
              sb + SW_L + rb);
      }
#pragma unroll
      for (int mt = 0; mt < 4; mt++)
#pragma unroll
        for (int nt = 0; nt < 4; nt++) {
          float* c = acc[mt][nt];
          mma_bf16(c[0], c[1], c[2], c[3], ah[mt][0], ah[mt][1], ah[mt][2],
                   ah[mt][3], bh[nt * 2], bh[nt * 2 + 1]);
          mma_bf16(c[0], c[1], c[2], c[3], ah[mt][0], ah[mt][1], ah[mt][2],
                   ah[mt][3], bl[nt * 2], bl[nt * 2 + 1]);
          mma_bf16(c[0], c[1], c[2], c[3], al[mt][0], al[mt][1], al[mt][2],
                   al[mt][3], bh[nt * 2], bh[nt * 2 + 1]);
        }
    }
  }

  const int er = l >> 2, ec = (l & 3) * 2;
#pragma unroll
  for (int mt = 0; mt < 4; mt++) {
    int row = m0 + wm * 64 + mt * 16 + er;
#pragma unroll
    for (int nt = 0; nt < 4; nt++) {
      int col = n0 + wn * 32 + nt * 8 + ec;
      float* a = acc[mt][nt];
      if constexpr (SPLIT) {
        float h0 = __bfloat162float(__float2bfloat16(a[0]));
        float h1 = __bfloat162float(__float2bfloat16(a[1]));
        float h2 = __bfloat162float(__float2bfloat16(a[2]));
        float h3 = __bfloat162float(__float2bfloat16(a[3]));
        size_t i0 = (size_t)row * HID + col;
        size_t i1 = (size_t)(row + 8) * HID + col;
        *(uint32_t*)&p.ch[z][i0] = pack_bf16(a[0], a[1]);
        *(uint32_t*)&p.cl[z][i0] = pack_bf16(a[0] - h0, a[1] - h1);
        *(uint32_t*)&p.ch[z][i1] = pack_bf16(a[2], a[3]);
        *(uint32_t*)&p.cl[z][i1] = pack_bf16(a[2] - h2, a[3] - h3);
      } else {
        *(float2*)&p.c[(size_t)row * HID + col] = make_float2(a[0], a[1]);
        *(float2*)&p.c[(size_t)(row + 8) * HID + col] =
            make_float2(a[2], a[3]);
      }
    }
  }
}

// ---------------------------------------------------------------------------
// HMMA flash attention (bf16x3, fp32 softmax) — unchanged (at mma ceiling).
// ---------------------------------------------------------------------------
constexpr int AQ_H = 0;                        // Q hi: 128 x 144B
constexpr int AQ_L = 128 * RS * 2;             // 18432
constexpr int STG0 = 2 * 128 * RS * 2;         // 36864
constexpr int KV_COMP = 64 * RS * 2;           // 9216 per component
constexpr int STG_SZ = 4 * KV_COMP;            // 36864
constexpr int ATTN_SMEM = STG0 + 2 * STG_SZ;   // 110592

__global__ __launch_bounds__(256, 2) void attn_hmma(
    const __nv_bfloat16* __restrict__ Qh, const __nv_bfloat16* __restrict__ Ql,
    const __nv_bfloat16* __restrict__ Kh, const __nv_bfloat16* __restrict__ Kl,
    const __nv_bfloat16* __restrict__ Vh, const __nv_bfloat16* __restrict__ Vl,
    const int* __restrict__ valid_lens, __nv_bfloat16* __restrict__ Oh,
    __nv_bfloat16* __restrict__ Ol) {
  extern __shared__ __align__(128) char smem[];
  const uint32_t sb = smem_u32(smem);
  const int qt = blockIdx.x, h = blockIdx.y, b = blockIdx.z;
  const int t = threadIdx.x;
  const int wid = t >> 5, l = t & 31;
  const int q0 = qt * 128;
  const int vlen = valid_lens[b];
  const int ntiles = (vlen + 63) >> 6;

  const __nv_bfloat16* kv_src[4] = {Kh, Kl, Vh, Vl};

  auto issue_tile = [&](int stage, int kbase) {
#pragma unroll
    for (int i = 0; i < 8; i++) {
      int idx = t + i * 256;
      int comp = idx >> 9;
      int r = (idx >> 3) & 63;
      int c = idx & 7;
      const __nv_bfloat16* src =
          kv_src[comp] + (size_t)(b * S + kbase + r) * HID + h * DH + c * 8;
      uint32_t dst =
          sb + STG0 + stage * STG_SZ + comp * KV_COMP + r * (RS * 2) + c * 16;
      CP_ASYNC16(dst, src);
    }
  };

  issue_tile(0, 0);
  CP_COMMIT();
#pragma unroll
  for (int i = 0; i < 4; i++) {
    int v = t + i * 256;
    int row = v >> 3, c = v & 7;
    size_t g = (size_t)(b * S + q0 + row) * HID + h * DH + c * 8;
    uint32_t so = row * (RS * 2) + c * 16;
    *(uint4*)(smem + AQ_H + so) = *(const uint4*)(Qh + g);
    *(uint4*)(smem + AQ_L + so) = *(const uint4*)(Ql + g);
  }
  __syncthreads();

  const int a_row = (l & 15);
  const int a_koff = ((l >> 4) & 1) * 16;
  const int b_row = (l & 7) + ((l >> 4) & 1) * 8;
  const int b_koff = ((l >> 3) & 1) * 16;
  const int v_row = (l & 7) + ((l >> 3) & 1) * 8;
  const int v_col = ((l >> 4) & 1) * 16;
  const int cb = (l & 3) * 2;

  uint32_t qh[4][4], ql[4][4];
#pragma unroll
  for (int ks = 0; ks < 4; ks++) {
    uint32_t ra = (wid * 16 + a_row) * (RS * 2) + ks * 32 + a_koff;
    LDMX4(qh[ks][0], qh[ks][1], qh[ks][2], qh[ks][3], sb + AQ_H + ra);
    LDMX4(ql[ks][0], ql[ks][1], ql[ks][2], ql[ks][3], sb + AQ_L + ra);
  }

  float oacc[8][4] = {};
  float m0r = -1e30f, m1r = -1e30f, l0r = 0.f, l1r = 0.f;

  for (int kt = 0; kt < ntiles; kt++) {
    const int kbase = kt * 64;
    const uint32_t kb_h = sb + STG0 + (kt & 1) * STG_SZ;
    const uint32_t kb_l = kb_h + KV_COMP;
    const uint32_t vb_h = kb_h + 2 * KV_COMP;
    const uint32_t vb_l = kb_h + 3 * KV_COMP;

    CP_WAIT0();
    __syncthreads();
    if (kt + 1 < ntiles) {
      issue_tile((kt + 1) & 1, kbase + 64);
      CP_COMMIT();
    }

    float sc[8][4];
#pragma unroll
    for (int nt = 0; nt < 8; nt++)
#pragma unroll
      for (int c = 0; c < 4; c++) sc[nt][c] = 0.f;
#pragma unroll
    for (int ks = 0; ks < 4; ks++) {
      uint32_t khf[16], klf[16];
#pragma unroll
      for (int np = 0; np < 4; np++) {
        uint32_t rb = (np * 16 + b_row) * (RS * 2) + ks * 32 + b_koff;
        LDMX4(khf[np * 4 + 0], khf[np * 4 + 1], khf[np * 4 + 2],
              khf[np * 4 + 3], kb_h + rb);
        LDMX4(klf[np * 4 + 0], klf[np * 4 + 1], klf[np * 4 + 2],
              klf[np * 4 + 3], kb_l + rb);
      }
#pragma unroll
      for (int nt = 0; nt < 8; nt++) {
        float* c = sc[nt];
        mma_bf16(c[0], c[1], c[2], c[3], qh[ks][0], qh[ks][1], qh[ks][2],
                 qh[ks][3], khf[nt * 2], khf[nt * 2 + 1]);
        mma_bf16(c[0], c[1], c[2], c[3], qh[ks][0], qh[ks][1], qh[ks][2],
                 qh[ks][3], klf[nt * 2], klf[nt * 2 + 1]);
        mma_bf16(c[0], c[1], c[2], c[3], ql[ks][0], ql[ks][1], ql[ks][2],
                 ql[ks][3], khf[nt * 2], khf[nt * 2 + 1]);
      }
    }

#pragma unroll
    for (int nt = 0; nt < 8; nt++)
#pragma unroll
      for (int c = 0; c < 4; c++) sc[nt][c] *= 0.125f;
    if (kbase + 64 > vlen) {
#pragma unroll
      for (int nt = 0; nt < 8; nt++) {
        int k0 = kbase + nt * 8 + cb;
        if (k0 >= vlen) { sc[nt][0] = -1e30f; sc[nt][2] = -1e30f; }
        if (k0 + 1 >= vlen) { sc[nt][1] = -1e30f; sc[nt][3] = -1e30f; }
      }
    }

    float rm0 = -1e30f, rm1 = -1e30f;
#pragma unroll
    for (int nt = 0; nt < 8; nt++) {
      rm0 = fmaxf(rm0, fmaxf(sc[nt][0], sc[nt][1]));
      rm1 = fmaxf(rm1, fmaxf(sc[nt][2], sc[nt][3]));
    }
    rm0 = fmaxf(rm0, __shfl_xor_sync(0xffffffffu, rm0, 1));
    rm0 = fmaxf(rm0, __shfl_xor_sync(0xffffffffu, rm0, 2));
    rm1 = fmaxf(rm1, __shfl_xor_sync(0xffffffffu, rm1, 1));
    rm1 = fmaxf(rm1, __shfl_xor_sync(0xffffffffu, rm1, 2));
    float mn0 = fmaxf(m0r, rm0), mn1 = fmaxf(m1r, rm1);
    float corr0 = __expf(m0r - mn0), corr1 = __expf(m1r - mn1);

    uint32_t ph[8][2], pl[8][2];
    float rs0 = 0.f, rs1 = 0.f;
#pragma unroll
    for (int nt = 0; nt < 8; nt++) {
      float p0 = __expf(sc[nt][0] - mn0);
      float p1 = __expf(sc[nt][1] - mn0);
      float p2 = __expf(sc[nt][2] - mn1);
      float p3 = __expf(sc[nt][3] - mn1);
      rs0 += p0 + p1;
      rs1 += p2 + p3;
      float h0 = __bfloat162float(__float2bfloat16(p0));
      float h1 = __bfloat162float(__float2bfloat16(p1));
      float h2 = __bfloat162float(__float2bfloat16(p2));
      float h3 = __bfloat162float(__float2bfloat16(p3));
      ph[nt][0] = pack_bf16(p0, p1);
      ph[nt][1] = pack_bf16(p2, p3);
      pl[nt][0] = pack_bf16(p0 - h0, p1 - h1);
      pl[nt][1] = pack_bf16(p2 - h2, p3 - h3);
    }
    rs0 += __shfl_xor_sync(0xffffffffu, rs0, 1);
    rs0 += __shfl_xor_sync(0xffffffffu, rs0, 2);
    rs1 += __shfl_xor_sync(0xffffffffu, rs1, 1);
    rs1 += __shfl_xor_sync(0xffffffffu, rs1, 2);
    l0r = l0r * corr0 + rs0;
    l1r = l1r * corr1 + rs1;
    m0r = mn0;
    m1r = mn1;
#pragma unroll
    for (int nt = 0; nt < 8; nt++) {
      oacc[nt][0] *= corr0;
      oacc[nt][1] *= corr0;
      oacc[nt][2] *= corr1;
      oacc[nt][3] *= corr1;
    }

#pragma unroll
    for (int ks = 0; ks < 4; ks++) {
      uint32_t vhf[16], vlf[16];
#pragma unroll
      for (int np = 0; np < 4; np++) {
        uint32_t rv = (ks * 16 + v_row) * (RS * 2) + np * 32 + v_col;
        LDMX4T(vhf[np * 4 + 0], vhf[np * 4 + 1], vhf[np * 4 + 2],
               vhf[np * 4 + 3], vb_h + rv);
        LDMX4T(vlf[np * 4 + 0], vlf[np * 4 + 1], vlf[np * 4 + 2],
               vlf[np * 4 + 3], vb_l + rv);
      }
      uint32_t a0 = ph[2 * ks][0], a1 = ph[2 * ks][1];
      uint32_t a2 = ph[2 * ks + 1][0], a3 = ph[2 * ks + 1][1];
      uint32_t e0 = pl[2 * ks][0], e1 = pl[2 * ks][1];
      uint32_t e2 = pl[2 * ks + 1][0], e3 = pl[2 * ks + 1][1];
#pragma unroll
      for (int nt = 0; nt < 8; nt++) {
        float* c = oacc[nt];
        mma_bf16(c[0], c[1], c[2], c[3], a0, a1, a2, a3, vhf[nt * 2],
                 vhf[nt * 2 + 1]);
        mma_bf16(c[0], c[1], c[2], c[3], a0, a1, a2, a3, vlf[nt * 2],
                 vlf[nt * 2 + 1]);
        mma_bf16(c[0], c[1], c[2], c[3], e0, e1, e2, e3, vhf[nt * 2],
                 vhf[nt * 2 + 1]);
      }
    }
  }

  float inv0 = 1.f / l0r, inv1 = 1.f / l1r;
  int r0 = q0 + wid * 16 + (l >> 2);
#pragma unroll
  for (int nt = 0; nt < 8; nt++) {
    int col = h * DH + nt * 8 + cb;
    float o0 = oacc[nt][0] * inv0, o1 = oacc[nt][1] * inv0;
    float o2 = oacc[nt][2] * inv1, o3 = oacc[nt][3] * inv1;
    float h0 = __bfloat162float(__float2bfloat16(o0));
    float h1 = __bfloat162float(__float2bfloat16(o1));
    float h2 = __bfloat162float(__float2bfloat16(o2));
    float h3 = __bfloat162float(__float2bfloat16(o3));
    size_t i0 = (size_t)(b * S + r0) * HID + col;
    size_t i1 = (size_t)(b * S + r0 + 8) * HID + col;
    *(uint32_t*)&Oh[i0] = pack_bf16(o0, o1);
    *(uint32_t*)&Ol[i0] = pack_bf16(o0 - h0, o1 - h1);
    *(uint32_t*)&Oh[i1] = pack_bf16(o2, o3);
    *(uint32_t*)&Ol[i1] = pack_bf16(o2 - h2, o3 - h3);
  }
}

// ---------------------------------------------------------------------------
extern "C" void kernel_launch(void* const* d_in, const int* in_sizes, int n_in,
                              void* d_out, int out_size) {
  const float* queries = (const float*)d_in[0];
  const float* keys    = (const float*)d_in[1];
  const float* values  = (const float*)d_in[2];
  const int*   vlens   = (const int*)d_in[3];
  const float* W[4]    = {(const float*)d_in[4], (const float*)d_in[5],
                          (const float*)d_in[6], (const float*)d_in[7]};
  float* out = (float*)d_out;

  __nv_bfloat16 *whb, *wlb, *qh, *ql, *kh, *kl, *vh, *vl, *oh, *ol;
  cudaGetSymbolAddress((void**)&whb, g_wh);
  cudaGetSymbolAddress((void**)&wlb, g_wl);
  cudaGetSymbolAddress((void**)&qh, g_qh);
  cudaGetSymbolAddress((void**)&ql, g_ql);
  cudaGetSymbolAddress((void**)&kh, g_kh);
  cudaGetSymbolAddress((void**)&kl, g_kl);
  cudaGetSymbolAddress((void**)&vh, g_vh);
  cudaGetSymbolAddress((void**)&vl, g_vl);
  cudaGetSymbolAddress((void**)&oh, g_oh);
  cudaGetSymbolAddress((void**)&ol, g_ol);
  const int WSZ = HID * HID;

  cudaFuncSetAttribute(gemm_tc_hmma<true, true>,
                       cudaFuncAttributeMaxDynamicSharedMemorySize, GEMM_SMEM);
  cudaFuncSetAttribute(gemm_tc_hmma<false, false>,
                       cudaFuncAttributeMaxDynamicSharedMemorySize, GEMM_SMEM);
  cudaFuncSetAttribute(attn_hmma,
                       cudaFuncAttributeMaxDynamicSharedMemorySize, ATTN_SMEM);

  // --- one batched weight split (Wq, Wk, Wv, Wo) ---
  SplitBatch wsb = {};
  for (int i = 0; i < 4; i++) {
    wsb.src[i] = W[i];
    wsb.hi[i] = whb + i * WSZ;
    wsb.lo[i] = wlb + i * WSZ;
  }
  split_batch_kernel<<<dim3(WSZ / 4 / 256, 4), 256>>>(wsb, WSZ / 4);

  // --- Q/K/V projections in ONE launch (grid.z = 3, 768 CTAs) ---
  GemmBatch gp = {};
  gp.af[0] = queries; gp.af[1] = keys; gp.af[2] = values;
  for (int i = 0; i < 3; i++) {
    gp.wh[i] = whb + i * WSZ;
    gp.wl[i] = wlb + i * WSZ;
  }
  gp.ch[0] = qh; gp.cl[0] = ql;
  gp.ch[1] = kh; gp.cl[1] = kl;
  gp.ch[2] = vh; gp.cl[2] = vl;
  gemm_tc_hmma<true, true>
      <<<dim3(HID / 128, M / 128, 3), 256, GEMM_SMEM>>>(gp);

  // --- attention ---
  attn_hmma<<<dim3(S / 128, NH, B), 256, ATTN_SMEM>>>(qh, ql, kh, kl, vh, vl,
                                                      vlens, oh, ol);

  // --- output projection (bf16 hi/lo A, fp32 out) ---
  GemmBatch go = {};
  go.ah = oh; go.al = ol;
  go.wh[0] = whb + 3 * WSZ;
  go.wl[0] = wlb + 3 * WSZ;
  go.c = out;
  gemm_tc_hmma<false, false>
      <<<dim3(HID / 128, M / 128, 1), 256, GEMM_SMEM>>>(go);
}

// round 9
// speedup vs baseline: 1.1778x; 1.0018x over previous
#include <cuda_runtime.h>
#include <cuda_bf16.h>
#include <cstdint>

// Problem constants
constexpr int B   = 4;
constexpr int S   = 2048;
constexpr int HID = 512;
constexpr int NH  = 8;
constexpr int DH  = 64;
constexpr int M   = B * S;       // 8192

// Scratch (device globals — no runtime allocation allowed)
__device__ __nv_bfloat16 g_wh[4][HID * HID], g_wl[4][HID * HID];
__device__ __nv_bfloat16 g_qh[M * HID], g_ql[M * HID];
__device__ __nv_bfloat16 g_kh[M * HID], g_kl[M * HID];
__device__ __nv_bfloat16 g_vh[M * HID], g_vl[M * HID];
__device__ __nv_bfloat16 g_oh[M * HID], g_ol[M * HID];

// ---------------------------------------------------------------------------
// mma.sync / ldmatrix / cp.async helpers (plain sm_80+ PTX)
// ---------------------------------------------------------------------------
__device__ __forceinline__ uint32_t smem_u32(const void* p) {
  uint32_t a;
  asm("{ .reg .u64 t; cvta.to.shared.u64 t, %1; cvt.u32.u64 %0, t; }"
      : "=r"(a) : "l"(p));
  return a;
}

#define LDMX4(r0, r1, r2, r3, addr)                                       \
  asm volatile(                                                           \
      "ldmatrix.sync.aligned.m8n8.x4.shared.b16 {%0,%1,%2,%3}, [%4];"     \
      : "=r"(r0), "=r"(r1), "=r"(r2), "=r"(r3) : "r"(addr))

#define LDMX4T(r0, r1, r2, r3, addr)                                      \
  asm volatile(                                                           \
      "ldmatrix.sync.aligned.m8n8.x4.trans.shared.b16 {%0,%1,%2,%3}, [%4];" \
      : "=r"(r0), "=r"(r1), "=r"(r2), "=r"(r3) : "r"(addr))

#define CP_ASYNC16(dst, src)                                              \
  asm volatile("cp.async.cg.shared.global [%0], [%1], 16;" ::             \
                   "r"(dst), "l"(src))
#define CP_COMMIT() asm volatile("cp.async.commit_group;" ::: "memory")
#define CP_WAIT0() asm volatile("cp.async.wait_group 0;" ::: "memory")
#define CP_WAIT1() asm volatile("cp.async.wait_group 1;" ::: "memory")

__device__ __forceinline__ void mma_bf16(float& c0, float& c1, float& c2,
                                         float& c3, uint32_t a0, uint32_t a1,
                                         uint32_t a2, uint32_t a3,
                                         uint32_t b0, uint32_t b1) {
  asm volatile(
      "mma.sync.aligned.m16n8k16.row.col.f32.bf16.bf16.f32 "
      "{%0,%1,%2,%3}, {%4,%5,%6,%7}, {%8,%9}, {%0,%1,%2,%3};"
      : "+f"(c0), "+f"(c1), "+f"(c2), "+f"(c3)
      : "r"(a0), "r"(a1), "r"(a2), "r"(a3), "r"(b0), "r"(b1));
}

__device__ __forceinline__ uint32_t pack_bf16(float a, float b) {
  __nv_bfloat162 t = __floats2bfloat162_rn(a, b);
  return *(uint32_t*)&t;
}

// ---------------------------------------------------------------------------
// fp32 -> (bf16 hi, bf16 lo) split, batched over blockIdx.y (weights).
// ---------------------------------------------------------------------------
struct SplitBatch {
  const float* src[4];
  __nv_bfloat16* hi[4];
  __nv_bfloat16* lo[4];
};

__global__ __launch_bounds__(256) void split_batch_kernel(SplitBatch sb,
                                                          int n4) {
  int i = blockIdx.x * blockDim.x + threadIdx.x;
  if (i >= n4) return;
  int z = blockIdx.y;
  float4 v = ((const float4*)sb.src[z])[i];
  float hx = __bfloat162float(__float2bfloat16(v.x));
  float hy = __bfloat162float(__float2bfloat16(v.y));
  float hz = __bfloat162float(__float2bfloat16(v.z));
  float hw = __bfloat162float(__float2bfloat16(v.w));
  uint2 ho, lw;
  ho.x = pack_bf16(v.x, v.y);
  ho.y = pack_bf16(v.z, v.w);
  lw.x = pack_bf16(v.x - hx, v.y - hy);
  lw.y = pack_bf16(v.z - hz, v.w - hw);
  ((uint2*)sb.hi[z])[i] = ho;
  ((uint2*)sb.lo[z])[i] = lw;
}

// ---------------------------------------------------------------------------
// HMMA bf16x3 GEMM-NT: C = A @ W^T with fp32-equivalent accuracy.
// CTA 128x128, 8 warps, warp 64x32 (4x4 m16n8k16). K chunks of 64.
// W operand: cp.async DOUBLE-BUFFERED (2 stages x 36KB) — W load latency is
// overlapped with compute one chunk ahead. A operand: single-stage 36KB
// (AFP32: fused fp32->hi/lo conversion; else cp.async in the same group
// discipline). Total smem 110.6KB -> 2 CTAs/SM still fit.
// grid.z batches independent GEMMs into one launch.
// ---------------------------------------------------------------------------
constexpr int RS = 72;                    // smem row stride in bf16 (144 B)
constexpr int TILE_BYTES = 128 * RS * 2;  // 18432 per tile
constexpr int SA_H = 0;
constexpr int SA_L = TILE_BYTES;
constexpr int SW_BASE = 2 * TILE_BYTES;   // 36864
constexpr int W_STG = 2 * TILE_BYTES;     // Wh+Wl per stage
constexpr int GEMM_SMEM = SW_BASE + 2 * W_STG;  // 110592

struct GemmBatch {
  const float* af[3];                 // AFP32 inputs
  const __nv_bfloat16* ah;            // !AFP32 input (out-proj)
  const __nv_bfloat16* al;
  const __nv_bfloat16* wh[3];
  const __nv_bfloat16* wl[3];
  __nv_bfloat16* ch[3];               // SPLIT outputs
  __nv_bfloat16* cl[3];
  float* c;                           // !SPLIT output
};

template <bool AFP32, bool SPLIT>
__global__ __launch_bounds__(256, 2) void gemm_tc_hmma(GemmBatch p) {
  extern __shared__ __align__(128) char smem[];
  const uint32_t sb = smem_u32(smem);
  const int t = threadIdx.x;
  const int wid = t >> 5, l = t & 31;
  const int wm = wid >> 2;
  const int wn = wid & 3;
  const int m0 = blockIdx.y * 128;
  const int n0 = blockIdx.x * 128;
  const int z = blockIdx.z;

  const __nv_bfloat16* Wh = p.wh[z];
  const __nv_bfloat16* Wl = p.wl[z];

  // cp.async issue of one W chunk (Wh+Wl, 2048 x 16B across 256 threads)
  auto issue_w = [&](int stage, int kc) {
    const int koff = kc * 64;
#pragma unroll
    for (int i = 0; i < 8; i++) {
      int idx = t + i * 256;
      int comp = idx >> 10;             // 0: Wh, 1: Wl
      int r = (idx >> 3) & 127;
      int c = idx & 7;
      const __nv_bfloat16* src =
          (comp ? Wl : Wh) + (size_t)(n0 + r) * HID + koff + c * 8;
      uint32_t dst = sb + SW_BASE + stage * W_STG + comp * TILE_BYTES +
                     r * (RS * 2) + c * 16;
      CP_ASYNC16(dst, src);
    }
  };

  issue_w(0, 0);
  CP_COMMIT();

  float acc[4][4][4] = {};

  const int a_row = (l & 15);
  const int a_koff = ((l >> 4) & 1) * 16;
  const int b_row = (l & 7) + ((l >> 4) & 1) * 8;
  const int b_koff = ((l >> 3) & 1) * 16;

  for (int kc = 0; kc < 8; kc++) {
    const int koff = kc * 64;
    // --- A chunk kc into the (single-stage) A region ---
    if constexpr (AFP32) {
      const float* Af = p.af[z];
#pragma unroll
      for (int i = 0; i < 8; i++) {     // 2048 float4
        int v = t + i * 256;
        int row = v >> 4, c = v & 15;
        float4 fv = *(const float4*)(Af + (size_t)(m0 + row) * HID + koff +
                                     c * 4);
        float hx = __bfloat162float(__float2bfloat16(fv.x));
        float hy = __bfloat162float(__float2bfloat16(fv.y));
        float hz = __bfloat162float(__float2bfloat16(fv.z));
        float hw = __bfloat162float(__float2bfloat16(fv.w));
        uint2 ho, lw;
        ho.x = pack_bf16(fv.x, fv.y);
        ho.y = pack_bf16(fv.z, fv.w);
        lw.x = pack_bf16(fv.x - hx, fv.y - hy);
        lw.y = pack_bf16(fv.z - hz, fv.w - hw);
        uint32_t so = row * (RS * 2) + c * 8;
        *(uint2*)(smem + SA_H + so) = ho;
        *(uint2*)(smem + SA_L + so) = lw;
      }
    } else {
#pragma unroll
      for (int i = 0; i < 8; i++) {     // 2048 x 16B cp.async
        int idx = t + i * 256;
        int comp = idx >> 10;           // 0: Ah, 1: Al
        int r = (idx >> 3) & 127;
        int c = idx & 7;
        const __nv_bfloat16* src =
            (comp ? p.al : p.ah) + (size_t)(m0 + r) * HID + koff + c * 8;
        uint32_t dst = sb + comp * TILE_BYTES + r * (RS * 2) + c * 16;
        CP_ASYNC16(dst, src);
      }
      CP_COMMIT();
    }
    // --- prefetch next W chunk; wait for this chunk's data ---
    if (kc + 1 < 8) {
      issue_w((kc + 1) & 1, kc + 1);
      CP_COMMIT();
      CP_WAIT1();                       // completes A_kc (if async) and W_kc
    } else {
      CP_WAIT0();
    }
    __syncthreads();
    const uint32_t st_w = sb + SW_BASE + (kc & 1) * W_STG;

#pragma unroll
    for (int ks = 0; ks < 4; ks++) {
      const int kb = ks * 32;
      uint32_t ah[4][4], al[4][4], bh[8], bl[8];
#pragma unroll
      for (int mt = 0; mt < 4; mt++) {
        uint32_t ra = (wm * 64 + mt * 16 + a_row) * (RS * 2) + kb + a_koff;
        LDMX4(ah[mt][0], ah[mt][1], ah[mt][2], ah[mt][3], sb + SA_H + ra);
        LDMX4(al[mt][0], al[mt][1], al[mt][2], al[mt][3], sb + SA_L + ra);
      }
#pragma unroll
      for (int np = 0; np < 2; np++) {
        uint32_t rb = (wn * 32 + np * 16 + b_row) * (RS * 2) + kb + b_koff;
        LDMX4(bh[np * 4 + 0], bh[np * 4 + 1], bh[np * 4 + 2], bh[np * 4 + 3],
              st_w + rb);
        LDMX4(bl[np * 4 + 0], bl[np * 4 + 1], bl[np * 4 + 2], bl[np * 4 + 3],
              st_w + TILE_BYTES + rb);
      }
#pragma unroll
      for (int mt = 0; mt < 4; mt++)
#pragma unroll
        for (int nt = 0; nt < 4; nt++) {
          float* c = acc[mt][nt];
          mma_bf16(c[0], c[1], c[2], c[3], ah[mt][0], ah[mt][1], ah[mt][2],
                   ah[mt][3], bh[nt * 2], bh[nt * 2 + 1]);
          mma_bf16(c[0], c[1], c[2], c[3], ah[mt][0], ah[mt][1], ah[mt][2],
                   ah[mt][3], bl[nt * 2], bl[nt * 2 + 1]);
          mma_bf16(c[0], c[1], c[2], c[3], al[mt][0], al[mt][1], al[mt][2],
                   al[mt][3], bh[nt * 2], bh[nt * 2 + 1]);
        }
    }
    __syncthreads();   // stage (kc+1)&1 and A region free for next iteration
  }

  const int er = l >> 2, ec = (l & 3) * 2;
#pragma unroll
  for (int mt = 0; mt < 4; mt++) {
    int row = m0 + wm * 64 + mt * 16 + er;
#pragma unroll
    for (int nt = 0; nt < 4; nt++) {
      int col = n0 + wn * 32 + nt * 8 + ec;
      float* a = acc[mt][nt];
      if constexpr (SPLIT) {
        float h0 = __bfloat162float(__float2bfloat16(a[0]));
        float h1 = __bfloat162float(__float2bfloat16(a[1]));
        float h2 = __bfloat162float(__float2bfloat16(a[2]));
        float h3 = __bfloat162float(__float2bfloat16(a[3]));
        size_t i0 = (size_t)row * HID + col;
        size_t i1 = (size_t)(row + 8) * HID + col;
        *(uint32_t*)&p.ch[z][i0] = pack_bf16(a[0], a[1]);
        *(uint32_t*)&p.cl[z][i0] = pack_bf16(a[0] - h0, a[1] - h1);
        *(uint32_t*)&p.ch[z][i1] = pack_bf16(a[2], a[3]);
        *(uint32_t*)&p.cl[z][i1] = pack_bf16(a[2] - h2, a[3] - h3);
      } else {
        *(float2*)&p.c[(size_t)row * HID + col] = make_float2(a[0], a[1]);
        *(float2*)&p.c[(size_t)(row + 8) * HID + col] =
            make_float2(a[2], a[3]);
      }
    }
  }
}

// ---------------------------------------------------------------------------
// HMMA flash attention (bf16x3, exp2-domain softmax).
// Scores are scaled once by (1/sqrt(DH))*log2(e); exp via exp2f — one fewer
// FMUL per score element in the serial softmax chain vs __expf.
// ---------------------------------------------------------------------------
constexpr float SC2 = 0.125f * 1.4426950408889634f;  // (1/8)*log2(e)

constexpr int AQ_H = 0;                        // Q hi: 128 x 144B
constexpr int AQ_L = 128 * RS * 2;             // 18432
constexpr int STG0 = 2 * 128 * RS * 2;         // 36864
constexpr int KV_COMP = 64 * RS * 2;           // 9216 per component
constexpr int STG_SZ = 4 * KV_COMP;            // 36864
constexpr int ATTN_SMEM = STG0 + 2 * STG_SZ;   // 110592

__global__ __launch_bounds__(256, 2) void attn_hmma(
    const __nv_bfloat16* __restrict__ Qh, const __nv_bfloat16* __restrict__ Ql,
    const __nv_bfloat16* __restrict__ Kh, const __nv_bfloat16* __restrict__ Kl,
    const __nv_bfloat16* __restrict__ Vh, const __nv_bfloat16* __restrict__ Vl,
    const int* __restrict__ valid_lens, __nv_bfloat16* __restrict__ Oh,
    __nv_bfloat16* __restrict__ Ol) {
  extern __shared__ __align__(128) char smem[];
  const uint32_t sb = smem_u32(smem);
  const int qt = blockIdx.x, h = blockIdx.y, b = blockIdx.z;
  const int t = threadIdx.x;
  const int wid = t >> 5, l = t & 31;
  const int q0 = qt * 128;
  const int vlen = valid_lens[b];
  const int ntiles = (vlen + 63) >> 6;

  const __nv_bfloat16* kv_src[4] = {Kh, Kl, Vh, Vl};

  auto issue_tile = [&](int stage, int kbase) {
#pragma unroll
    for (int i = 0; i < 8; i++) {
      int idx = t + i * 256;
      int comp = idx >> 9;
      int r = (idx >> 3) & 63;
      int c = idx & 7;
      const __nv_bfloat16* src =
          kv_src[comp] + (size_t)(b * S + kbase + r) * HID + h * DH + c * 8;
      uint32_t dst =
          sb + STG0 + stage * STG_SZ + comp * KV_COMP + r * (RS * 2) + c * 16;
      CP_ASYNC16(dst, src);
    }
  };

  issue_tile(0, 0);
  CP_COMMIT();
#pragma unroll
  for (int i = 0; i < 4; i++) {
    int v = t + i * 256;
    int row = v >> 3, c = v & 7;
    size_t g = (size_t)(b * S + q0 + row) * HID + h * DH + c * 8;
    uint32_t so = row * (RS * 2) + c * 16;
    *(uint4*)(smem + AQ_H + so) = *(const uint4*)(Qh + g);
    *(uint4*)(smem + AQ_L + so) = *(const uint4*)(Ql + g);
  }
  __syncthreads();

  const int a_row = (l & 15);
  const int a_koff = ((l >> 4) & 1) * 16;
  const int b_row = (l & 7) + ((l >> 4) & 1) * 8;
  const int b_koff = ((l >> 3) & 1) * 16;
  const int v_row = (l & 7) + ((l >> 3) & 1) * 8;
  const int v_col = ((l >> 4) & 1) * 16;
  const int cb = (l & 3) * 2;

  uint32_t qh[4][4], ql[4][4];
#pragma unroll
  for (int ks = 0; ks < 4; ks++) {
    uint32_t ra = (wid * 16 + a_row) * (RS * 2) + ks * 32 + a_koff;
    LDMX4(qh[ks][0], qh[ks][1], qh[ks][2], qh[ks][3], sb + AQ_H + ra);
    LDMX4(ql[ks][0], ql[ks][1], ql[ks][2], ql[ks][3], sb + AQ_L + ra);
  }

  float oacc[8][4] = {};
  float m0r = -1e30f, m1r = -1e30f, l0r = 0.f, l1r = 0.f;

  for (int kt = 0; kt < ntiles; kt++) {
    const int kbase = kt * 64;
    const uint32_t kb_h = sb + STG0 + (kt & 1) * STG_SZ;
    const uint32_t kb_l = kb_h + KV_COMP;
    const uint32_t vb_h = kb_h + 2 * KV_COMP;
    const uint32_t vb_l = kb_h + 3 * KV_COMP;

    CP_WAIT0();
    __syncthreads();
    if (kt + 1 < ntiles) {
      issue_tile((kt + 1) & 1, kbase + 64);
      CP_COMMIT();
    }

    float sc[8][4];
#pragma unroll
    for (int nt = 0; nt < 8; nt++)
#pragma unroll
      for (int c = 0; c < 4; c++) sc[nt][c] = 0.f;
#pragma unroll
    for (int ks = 0; ks < 4; ks++) {
      uint32_t khf[16], klf[16];
#pragma unroll
      for (int np = 0; np < 4; np++) {
        uint32_t rb = (np * 16 + b_row) * (RS * 2) + ks * 32 + b_koff;
        LDMX4(khf[np * 4 + 0], khf[np * 4 + 1], khf[np * 4 + 2],
              khf[np * 4 + 3], kb_h + rb);
        LDMX4(klf[np * 4 + 0], klf[np * 4 + 1], klf[np * 4 + 2],
              klf[np * 4 + 3], kb_l + rb);
      }
#pragma unroll
      for (int nt = 0; nt < 8; nt++) {
        float* c = sc[nt];
        mma_bf16(c[0], c[1], c[2], c[3], qh[ks][0], qh[ks][1], qh[ks][2],
                 qh[ks][3], khf[nt * 2], khf[nt * 2 + 1]);
        mma_bf16(c[0], c[1], c[2], c[3], qh[ks][0], qh[ks][1], qh[ks][2],
                 qh[ks][3], klf[nt * 2], klf[nt * 2 + 1]);
        mma_bf16(c[0], c[1], c[2], c[3], ql[ks][0], ql[ks][1], ql[ks][2],
                 ql[ks][3], khf[nt * 2], khf[nt * 2 + 1]);
      }
    }

#pragma unroll
    for (int nt = 0; nt < 8; nt++)
#pragma unroll
      for (int c = 0; c < 4; c++) sc[nt][c] *= SC2;   // exp2 domain
    if (kbase + 64 > vlen) {
#pragma unroll
      for (int nt = 0; nt < 8; nt++) {
        int k0 = kbase + nt * 8 + cb;
        if (k0 >= vlen) { sc[nt][0] = -1e30f; sc[nt][2] = -1e30f; }
        if (k0 + 1 >= vlen) { sc[nt][1] = -1e30f; sc[nt][3] = -1e30f; }
      }
    }

    float rm0 = -1e30f, rm1 = -1e30f;
#pragma unroll
    for (int nt = 0; nt < 8; nt++) {
      rm0 = fmaxf(rm0, fmaxf(sc[nt][0], sc[nt][1]));
      rm1 = fmaxf(rm1, fmaxf(sc[nt][2], sc[nt][3]));
    }
    rm0 = fmaxf(rm0, __shfl_xor_sync(0xffffffffu, rm0, 1));
    rm0 = fmaxf(rm0, __shfl_xor_sync(0xffffffffu, rm0, 2));
    rm1 = fmaxf(rm1, __shfl_xor_sync(0xffffffffu, rm1, 1));
    rm1 = fmaxf(rm1, __shfl_xor_sync(0xffffffffu, rm1, 2));
    float mn0 = fmaxf(m0r, rm0), mn1 = fmaxf(m1r, rm1);
    float corr0 = exp2f(m0r - mn0), corr1 = exp2f(m1r - mn1);

    uint32_t ph[8][2], pl[8][2];
    float rs0 = 0.f, rs1 = 0.f;
#pragma unroll
    for (int nt = 0; nt < 8; nt++) {
      float p0 = exp2f(sc[nt][0] - mn0);
      float p1 = exp2f(sc[nt][1] - mn0);
      float p2 = exp2f(sc[nt][2] - mn1);
      float p3 = exp2f(sc[nt][3] - mn1);
      rs0 += p0 + p1;
      rs1 += p2 + p3;
      float h0 = __bfloat162float(__float2bfloat16(p0));
      float h1 = __bfloat162float(__float2bfloat16(p1));
      float h2 = __bfloat162float(__float2bfloat16(p2));
      float h3 = __bfloat162float(__float2bfloat16(p3));
      ph[nt][0] = pack_bf16(p0, p1);
      ph[nt][1] = pack_bf16(p2, p3);
      pl[nt][0] = pack_bf16(p0 - h0, p1 - h1);
      pl[nt][1] = pack_bf16(p2 - h2, p3 - h3);
    }
    rs0 += __shfl_xor_sync(0xffffffffu, rs0, 1);
    rs0 += __shfl_xor_sync(0xffffffffu, rs0, 2);
    rs1 += __shfl_xor_sync(0xffffffffu, rs1, 1);
    rs1 += __shfl_xor_sync(0xffffffffu, rs1, 2);
    l0r = l0r * corr0 + rs0;
    l1r = l1r * corr1 + rs1;
    m0r = mn0;
    m1r = mn1;
#pragma unroll
    for (int nt = 0; nt < 8; nt++) {
      oacc[nt][0] *= corr0;
      oacc[nt][1] *= corr0;
      oacc[nt][2] *= corr1;
      oacc[nt][3] *= corr1;
    }

#pragma unroll
    for (int ks = 0; ks < 4; ks++) {
      uint32_t vhf[16], vlf[16];
#pragma unroll
      for (int np = 0; np < 4; np++) {
        uint32_t rv = (ks * 16 + v_row) * (RS * 2) + np * 32 + v_col;
        LDMX4T(vhf[np * 4 + 0], vhf[np * 4 + 1], vhf[np * 4 + 2],
               vhf[np * 4 + 3], vb_h + rv);
        LDMX4T(vlf[np * 4 + 0], vlf[np * 4 + 1], vlf[np * 4 + 2],
               vlf[np * 4 + 3], vb_l + rv);
      }
      uint32_t a0 = ph[2 * ks][0], a1 = ph[2 * ks][1];
      uint32_t a2 = ph[2 * ks + 1][0], a3 = ph[2 * ks + 1][1];
      uint32_t e0 = pl[2 * ks][0], e1 = pl[2 * ks][1];
      uint32_t e2 = pl[2 * ks + 1][0], e3 = pl[2 * ks + 1][1];
#pragma unroll
      for (int nt = 0; nt < 8; nt++) {
        float* c = oacc[nt];
        mma_bf16(c[0], c[1], c[2], c[3], a0, a1, a2, a3, vhf[nt * 2],
                 vhf[nt * 2 + 1]);
        mma_bf16(c[0], c[1], c[2], c[3], a0, a1, a2, a3, vlf[nt * 2],
                 vlf[nt * 2 + 1]);
        mma_bf16(c[0], c[1], c[2], c[3], e0, e1, e2, e3, vhf[nt * 2],
                 vhf[nt * 2 + 1]);
      }
    }
  }

  float inv0 = 1.f / l0r, inv1 = 1.f / l1r;
  int r0 = q0 + wid * 16 + (l >> 2);
#pragma unroll
  for (int nt = 0; nt < 8; nt++) {
    int col = h * DH + nt * 8 + cb;
    float o0 = oacc[nt][0] * inv0, o1 = oacc[nt][1] * inv0;
    float o2 = oacc[nt][2] * inv1, o3 = oacc[nt][3] * inv1;
    float h0 = __bfloat162float(__float2bfloat16(o0));
    float h1 = __bfloat162float(__float2bfloat16(o1));
    float h2 = __bfloat162float(__float2bfloat16(o2));
    float h3 = __bfloat162float(__float2bfloat16(o3));
    size_t i0 = (size_t)(b * S + r0) * HID + col;
    size_t i1 = (size_t)(b * S + r0 + 8) * HID + col;
    *(uint32_t*)&Oh[i0] = pack_bf16(o0, o1);
    *(uint32_t*)&Ol[i0] = pack_bf16(o0 - h0, o1 - h1);
    *(uint32_t*)&Oh[i1] = pack_bf16(o2, o3);
    *(uint32_t*)&Ol[i1] = pack_bf16(o2 - h2, o3 - h3);
  }
}

// ---------------------------------------------------------------------------
extern "C" void kernel_launch(void* const* d_in, const int* in_sizes, int n_in,
                              void* d_out, int out_size) {
  const float* queries = (const float*)d_in[0];
  const float* keys    = (const float*)d_in[1];
  const float* values  = (const float*)d_in[2];
  const int*   vlens   = (const int*)d_in[3];
  const float* W[4]    = {(const float*)d_in[4], (const float*)d_in[5],
                          (const float*)d_in[6], (const float*)d_in[7]};
  float* out = (float*)d_out;

  __nv_bfloat16 *whb, *wlb, *qh, *ql, *kh, *kl, *vh, *vl, *oh, *ol;
  cudaGetSymbolAddress((void**)&whb, g_wh);
  cudaGetSymbolAddress((void**)&wlb, g_wl);
  cudaGetSymbolAddress((void**)&qh, g_qh);
  cudaGetSymbolAddress((void**)&ql, g_ql);
  cudaGetSymbolAddress((void**)&kh, g_kh);
  cudaGetSymbolAddress((void**)&kl, g_kl);
  cudaGetSymbolAddress((void**)&vh, g_vh);
  cudaGetSymbolAddress((void**)&vl, g_vl);
  cudaGetSymbolAddress((void**)&oh, g_oh);
  cudaGetSymbolAddress((void**)&ol, g_ol);
  const int WSZ = HID * HID;

  cudaFuncSetAttribute(gemm_tc_hmma<true, true>,
                       cudaFuncAttributeMaxDynamicSharedMemorySize, GEMM_SMEM);
  cudaFuncSetAttribute(gemm_tc_hmma<false, false>,
                       cudaFuncAttributeMaxDynamicSharedMemorySize, GEMM_SMEM);
  cudaFuncSetAttribute(attn_hmma,
                       cudaFuncAttributeMaxDynamicSharedMemorySize, ATTN_SMEM);

  // --- one batched weight split (Wq, Wk, Wv, Wo) ---
  SplitBatch wsb = {};
  for (int i = 0; i < 4; i++) {
    wsb.src[i] = W[i];
    wsb.hi[i] = whb + i * WSZ;
    wsb.lo[i] = wlb + i * WSZ;
  }
  split_batch_kernel<<<dim3(WSZ / 4 / 256, 4), 256>>>(wsb, WSZ / 4);

  // --- Q/K/V projections in ONE launch (grid.z = 3, 768 CTAs) ---
  GemmBatch gp = {};
  gp.af[0] = queries; gp.af[1] = keys; gp.af[2] = values;
  for (int i = 0; i < 3; i++) {
    gp.wh[i] = whb + i * WSZ;
    gp.wl[i] = wlb + i * WSZ;
  }
  gp.ch[0] = qh; gp.cl[0] = ql;
  gp.ch[1] = kh; gp.cl[1] = kl;
  gp.ch[2] = vh; gp.cl[2] = vl;
  gemm_tc_hmma<true, true>
      <<<dim3(HID / 128, M / 128, 3), 256, GEMM_SMEM>>>(gp);

  // --- attention ---
  attn_hmma<<<dim3(S / 128, NH, B), 256, ATTN_SMEM>>>(qh, ql, kh, kl, vh, vl,
                                                      vlens, oh, ol);

  // --- output projection (bf16 hi/lo A, fp32 out) ---
  GemmBatch go = {};
  go.ah = oh; go.al = ol;
  go.wh[0] = whb + 3 * WSZ;
  go.wl[0] = wlb + 3 * WSZ;
  go.c = out;
  gemm_tc_hmma<false, false>
      <<<dim3(HID / 128, M / 128, 1), 256, GEMM_SMEM>>>(go);
}